// round 1
// baseline (speedup 1.0000x reference)
#include <cuda_runtime.h>
#include <cuda_bf16.h>
#include <cstdint>

// AFM layer: B=1024, N=64 fields, E=64, A=32, P = N*(N-1)/2 = 2016 pairs.
//   inner[p,e] = x[i_p,e]*x[j_p,e]
//   h = relu(inner @ W1 + b1); logits = h @ W2 + b2
//   attn = softmax(logits over p); out[e] = sum_p inner[p,e]*attn[p]
// Outputs (tuple): outputs (B,64) then attn_scores (B,2016,1), fp32.

#define NF 64
#define EDIM 64
#define ADIM 32
#define NPAIR 2016
#define NTHREADS 256

typedef unsigned long long ull;

__device__ __forceinline__ ull pk2(float lo, float hi) {
    ull r;
    asm("mov.b64 %0, {%1, %2};" : "=l"(r) : "f"(lo), "f"(hi));
    return r;
}
__device__ __forceinline__ void up2(ull v, float& lo, float& hi) {
    asm("mov.b64 {%0, %1}, %2;" : "=f"(lo), "=f"(hi) : "l"(v));
}
__device__ __forceinline__ ull fma2(ull a, ull b, ull c) {
    ull d;
    asm("fma.rn.f32x2 %0, %1, %2, %3;" : "=l"(d) : "l"(a), "l"(b), "l"(c));
    return d;
}

__global__ __launch_bounds__(NTHREADS, 1)
void afm_kernel(const float* __restrict__ x,    // (B, 64, 64)
                const float* __restrict__ W1,   // (64, 32)
                const float* __restrict__ b1,   // (32)
                const float* __restrict__ W2,   // (32, 1)
                const float* __restrict__ b2,   // (1)
                float* __restrict__ outP,       // (B, 64) or null
                float* __restrict__ attnP)      // (B, 2016) or null
{
    __shared__ float xs[NF * 65];            // padded: 16640 B
    __shared__ ull   w1d[EDIM * ADIM];       // duplicated {w,w}: 16384 B
    __shared__ float lg[NPAIR];              // logits -> exp -> attn: 8064 B
    __shared__ unsigned char iis[NPAIR];
    __shared__ unsigned char jjs[NPAIR];     // 4032 B
    __shared__ float b1s[ADIM];
    __shared__ float w2s[ADIM];
    __shared__ float b2s;
    __shared__ float red[8];
    __shared__ float outred[8][EDIM];        // 2048 B

    const int t    = threadIdx.x;
    const int lane = t & 31;
    const int warp = t >> 5;
    const int b    = blockIdx.x;

    // ---- load x tile (coalesced) ----
    const float* xb = x + (size_t)b * (NF * EDIM);
    for (int idx = t; idx < NF * EDIM; idx += NTHREADS) {
        int r = idx >> 6, c = idx & 63;
        xs[r * 65 + c] = xb[idx];
    }
    // ---- weights ----
    for (int idx = t; idx < EDIM * ADIM; idx += NTHREADS) {
        float w = W1[idx];
        w1d[idx] = pk2(w, w);
    }
    if (t < ADIM) { b1s[t] = b1[t]; w2s[t] = W2[t]; }
    if (t == 0)   { b2s = b2[0]; }
    // ---- pair index tables: row i holds pairs (i, i+1..63) ----
    if (t < NF - 1) {
        int i = t;
        int off = i * (NF - 1) - (i * (i - 1)) / 2;  // 63*i - i(i-1)/2
        int cnt = NF - 1 - i;
        for (int k = 0; k < cnt; k++) {
            iis[off + k] = (unsigned char)i;
            jjs[off + k] = (unsigned char)(i + 1 + k);
        }
    }
    __syncthreads();

    const float b2v = b2s;

    // ================= Phase 1: logits (two pairs per thread, f32x2) =======
    for (int pp = t; pp < NPAIR / 2; pp += NTHREADS) {
        const int p0 = pp * 2;
        const int i0 = iis[p0],     j0 = jjs[p0];
        const int i1 = iis[p0 + 1], j1 = jjs[p0 + 1];

        ull in2[EDIM];
        #pragma unroll
        for (int e = 0; e < EDIM; e++) {
            float a0 = xs[i0 * 65 + e] * xs[j0 * 65 + e];
            float a1 = xs[i1 * 65 + e] * xs[j1 * 65 + e];
            in2[e] = pk2(a0, a1);
        }

        float lg0 = b2v, lg1 = b2v;
        #pragma unroll 1
        for (int ab = 0; ab < ADIM / 4; ab++) {
            const int a0 = ab * 4;
            ull h0 = pk2(b1s[a0 + 0], b1s[a0 + 0]);
            ull h1 = pk2(b1s[a0 + 1], b1s[a0 + 1]);
            ull h2 = pk2(b1s[a0 + 2], b1s[a0 + 2]);
            ull h3 = pk2(b1s[a0 + 3], b1s[a0 + 3]);
            #pragma unroll
            for (int e = 0; e < EDIM; e++) {
                const ulonglong2 wA = *(const ulonglong2*)(w1d + e * ADIM + a0);
                const ulonglong2 wB = *(const ulonglong2*)(w1d + e * ADIM + a0 + 2);
                h0 = fma2(in2[e], wA.x, h0);
                h1 = fma2(in2[e], wA.y, h1);
                h2 = fma2(in2[e], wB.x, h2);
                h3 = fma2(in2[e], wB.y, h3);
            }
            float u, v;
            up2(h0, u, v); lg0 = fmaf(fmaxf(u, 0.f), w2s[a0 + 0], lg0); lg1 = fmaf(fmaxf(v, 0.f), w2s[a0 + 0], lg1);
            up2(h1, u, v); lg0 = fmaf(fmaxf(u, 0.f), w2s[a0 + 1], lg0); lg1 = fmaf(fmaxf(v, 0.f), w2s[a0 + 1], lg1);
            up2(h2, u, v); lg0 = fmaf(fmaxf(u, 0.f), w2s[a0 + 2], lg0); lg1 = fmaf(fmaxf(v, 0.f), w2s[a0 + 2], lg1);
            up2(h3, u, v); lg0 = fmaf(fmaxf(u, 0.f), w2s[a0 + 3], lg0); lg1 = fmaf(fmaxf(v, 0.f), w2s[a0 + 3], lg1);
        }
        lg[p0]     = lg0;
        lg[p0 + 1] = lg1;
    }
    __syncthreads();

    // ================= Phase 2: softmax over 2016 pairs ====================
    // max
    float lmax = -3.402823466e+38f;
    for (int p = t; p < NPAIR; p += NTHREADS) lmax = fmaxf(lmax, lg[p]);
    #pragma unroll
    for (int o = 16; o > 0; o >>= 1) lmax = fmaxf(lmax, __shfl_xor_sync(0xFFFFFFFFu, lmax, o));
    if (lane == 0) red[warp] = lmax;
    __syncthreads();
    if (t == 0) {
        float m = red[0];
        #pragma unroll
        for (int w = 1; w < 8; w++) m = fmaxf(m, red[w]);
        red[0] = m;
    }
    __syncthreads();
    const float gmax = red[0];
    __syncthreads();

    // exp + sum
    float lsum = 0.f;
    for (int p = t; p < NPAIR; p += NTHREADS) {
        float ev = expf(lg[p] - gmax);
        lg[p] = ev;
        lsum += ev;
    }
    #pragma unroll
    for (int o = 16; o > 0; o >>= 1) lsum += __shfl_xor_sync(0xFFFFFFFFu, lsum, o);
    if (lane == 0) red[warp] = lsum;
    __syncthreads();
    if (t == 0) {
        float s = 0.f;
        #pragma unroll
        for (int w = 0; w < 8; w++) s += red[w];
        red[0] = 1.0f / s;
    }
    __syncthreads();
    const float inv = red[0];

    // normalize, write attn
    for (int p = t; p < NPAIR; p += NTHREADS) {
        float av = lg[p] * inv;
        lg[p] = av;
        if (attnP) attnP[(size_t)b * NPAIR + p] = av;
    }
    __syncthreads();

    // ================= Phase 3: weighted sum over pairs ====================
    if (outP) {
        float acc[EDIM];
        #pragma unroll
        for (int e = 0; e < EDIM; e++) acc[e] = 0.f;

        for (int p = t; p < NPAIR; p += NTHREADS) {
            const int i = iis[p], j = jjs[p];
            const float w = lg[p];
            #pragma unroll
            for (int e = 0; e < EDIM; e++) {
                acc[e] = fmaf(xs[i * 65 + e] * xs[j * 65 + e], w, acc[e]);
            }
        }
        // warp butterfly reduce each element (deterministic)
        #pragma unroll
        for (int e = 0; e < EDIM; e++) {
            #pragma unroll
            for (int o = 16; o > 0; o >>= 1)
                acc[e] += __shfl_xor_sync(0xFFFFFFFFu, acc[e], o);
        }
        if (lane == 0) {
            #pragma unroll
            for (int e = 0; e < EDIM; e++) outred[warp][e] = acc[e];
        }
        __syncthreads();
        if (t < EDIM) {
            float s = 0.f;
            #pragma unroll
            for (int w = 0; w < 8; w++) s += outred[w][t];
            outP[(size_t)b * EDIM + t] = s;
        }
    }
}

extern "C" void kernel_launch(void* const* d_in, const int* in_sizes, int n_in,
                              void* d_out, int out_size) {
    const float* x  = (const float*)d_in[0];
    const float* W1 = (const float*)d_in[1];
    const float* b1 = (const float*)d_in[2];
    const float* W2 = (const float*)d_in[3];
    const float* b2 = (const float*)d_in[4];

    const int B = in_sizes[0] / (NF * EDIM);

    float* outP  = (float*)d_out;
    float* attnP = (float*)d_out + (size_t)B * EDIM;
    if (out_size == B * NPAIR) {           // attn only
        attnP = (float*)d_out;
        outP  = nullptr;
    } else if (out_size == B * EDIM) {     // outputs only
        attnP = nullptr;
    }

    afm_kernel<<<B, NTHREADS>>>(x, W1, b1, W2, b2, outP, attnP);
}

// round 3
// speedup vs baseline: 1.0640x; 1.0640x over previous
#include <cuda_runtime.h>
#include <cuda_bf16.h>
#include <cstdint>

// AFM layer: B=1024, N=64 fields, E=64, A=32, P = 2016 pairs (padded to 2048).
//   inner[p,e] = x[i_p,e]*x[j_p,e]
//   h = relu(inner @ W1 + b1); logits = h @ W2 + b2
//   attn = softmax(logits over p); out[e] = sum_p inner[p,e]*attn[p]
// Outputs (tuple): outputs (B,64) then attn_scores (B,2016,1), fp32.

#define NF 64
#define EDIM 64
#define ADIM 32
#define NPAIR 2016
#define NPAD 2048
#define PC 512        // pairs per chunk
#define NCHUNK 4
#define ISTR 516      // inner_s row stride in floats (16B-aligned, bank-skewed)
#define XSTR 66       // xs row stride in floats (even -> 8B aligned f32x2)
#define NTHREADS 256

typedef unsigned long long ull;

__device__ __forceinline__ ull pk2(float lo, float hi) {
    ull r; asm("mov.b64 %0, {%1, %2};" : "=l"(r) : "f"(lo), "f"(hi)); return r;
}
__device__ __forceinline__ void up2(ull v, float& lo, float& hi) {
    asm("mov.b64 {%0, %1}, %2;" : "=f"(lo), "=f"(hi) : "l"(v));
}
__device__ __forceinline__ ull fma2(ull a, ull b, ull c) {
    ull d; asm("fma.rn.f32x2 %0, %1, %2, %3;" : "=l"(d) : "l"(a), "l"(b), "l"(c)); return d;
}

// dynamic smem layout (bytes):
//   w1d   : ull[2048]        @ 0        (16384)  duplicated+swizzled W1
//   inner : float[64*516]    @ 16384    (132096) one 512-pair chunk, [e][pack]
//   xs    : float[64*66]     @ 148480   (16896)  x tile, row stride 66
//   lg    : float[2048]      @ 165376   (8192)   logits -> attn
//   ijp   : ushort[2048]     @ 173568   (4096)   (i<<8|j) per pair
#define SMEM_DYN 177664

__global__ __launch_bounds__(NTHREADS, 1)
void afm_kernel(const float* __restrict__ x,    // (B, 64, 64)
                const float* __restrict__ W1,   // (64, 32)
                const float* __restrict__ b1,   // (32)
                const float* __restrict__ W2,   // (32, 1)
                const float* __restrict__ b2,   // (1)
                float* __restrict__ outP,       // (B, 64) or null
                float* __restrict__ attnP)      // (B, 2016) or null
{
    extern __shared__ char smx[];
    ull*            w1d = (ull*)smx;
    float*          inn = (float*)(smx + 16384);
    float*          xs  = (float*)(smx + 148480);
    float*          lg  = (float*)(smx + 165376);
    unsigned short* ijp = (unsigned short*)(smx + 173568);

    __shared__ float b1s[ADIM];
    __shared__ float w2s[ADIM];
    __shared__ float b2s;
    __shared__ float red[8];
    __shared__ float outred[8][EDIM];

    const int t    = threadIdx.x;
    const int lane = t & 31;
    const int warp = t >> 5;
    const int b    = blockIdx.x;

    // ---- load x tile (coalesced in, stride-66 rows in smem) ----
    const float* xb = x + (size_t)b * (NF * EDIM);
    for (int idx = t; idx < NF * EDIM; idx += NTHREADS) {
        int r = idx >> 6, c = idx & 63;
        xs[r * XSTR + c] = xb[idx];
    }
    // ---- duplicated + swizzled W1: slot(e,sub,ag) = ulonglong2{dup w[e][ag*8+2sub], dup w[e][ag*8+2sub+1]} ----
    for (int idx = t; idx < EDIM * ADIM; idx += NTHREADS) {
        int e = idx >> 5, a = idx & 31;
        int ag = a >> 3, wi = a & 7, sub = wi >> 1, half = wi & 1;
        float w = W1[idx];
        w1d[(e * 16 + sub * 4 + ag) * 2 + half] = pk2(w, w);
    }
    if (t < ADIM) { b1s[t] = b1[t]; w2s[t] = W2[t]; }
    if (t == 0)   { b2s = b2[0]; }
    // ---- pair table: ijp[p] = (i<<8)|j, rows i with j=i+1..63; pad tail with 0 ----
    if (t < NF - 1) {
        int i = t;
        int off = i * (NF - 1) - (i * (i - 1)) / 2;
        int cnt = NF - 1 - i;
        for (int k = 0; k < cnt; k++)
            ijp[off + k] = (unsigned short)((i << 8) | (i + 1 + k));
    }
    if (t >= 224 && t < 256) ijp[NPAIR + (t - 224)] = 0;  // pads 2016..2047
    __syncthreads();

    const float b2v = b2s;
    const int ag = t & 3;        // a-group (low lane bits -> shfl reduce)
    const int pg = t >> 2;       // pair-group 0..63
    const int a0 = ag * 8;

    // ===================== chunks: materialize + GEMM ======================
    for (int c = 0; c < NCHUNK; c++) {
        // ---- materialize inner chunk: pack q=t holds pairs (c*512+t, c*512+t+256) ----
        {
            const int p_lo = c * PC + t;
            const int p_hi = p_lo + 256;
            const unsigned short ij0 = ijp[p_lo];
            const unsigned short ij1 = ijp[p_hi];
            const float* xi0 = xs + (ij0 >> 8) * XSTR;
            const float* xj0 = xs + (ij0 & 255) * XSTR;
            const float* xi1 = xs + (ij1 >> 8) * XSTR;
            const float* xj1 = xs + (ij1 & 255) * XSTR;
            float* op = inn + 2 * t;
            #pragma unroll 4
            for (int e = 0; e < EDIM; e++) {
                float f0 = xi0[e] * xj0[e];
                float f1 = xi1[e] * xj1[e];
                *(ull*)(op + e * ISTR) = pk2(f0, f1);
            }
        }
        __syncthreads();

        // ---- GEMM: thread tile 4 packs (8 pairs) x 8 a, f32x2 over pair dim ----
        {
            const float* inp = inn + pg * 8;               // packs pg*4..pg*4+3
            const ulonglong2* wb = ((const ulonglong2*)w1d) + ag;

            ull h[32];
            #pragma unroll
            for (int aa = 0; aa < 8; aa++) {
                ull bb = pk2(b1s[a0 + aa], b1s[a0 + aa]);
                h[aa] = bb; h[8 + aa] = bb; h[16 + aa] = bb; h[24 + aa] = bb;
            }

            #pragma unroll 4
            for (int e = 0; e < EDIM; e++) {
                const ulonglong2 iA = *(const ulonglong2*)(inp + e * ISTR);
                const ulonglong2 iB = *(const ulonglong2*)(inp + e * ISTR + 4);
                const ulonglong2* wr = wb + e * 16;
                #pragma unroll
                for (int sub = 0; sub < 4; sub++) {
                    const ulonglong2 wv = wr[sub * 4];
                    h[     sub * 2    ] = fma2(iA.x, wv.x, h[     sub * 2    ]);
                    h[     sub * 2 + 1] = fma2(iA.x, wv.y, h[     sub * 2 + 1]);
                    h[ 8 + sub * 2    ] = fma2(iA.y, wv.x, h[ 8 + sub * 2    ]);
                    h[ 8 + sub * 2 + 1] = fma2(iA.y, wv.y, h[ 8 + sub * 2 + 1]);
                    h[16 + sub * 2    ] = fma2(iB.x, wv.x, h[16 + sub * 2    ]);
                    h[16 + sub * 2 + 1] = fma2(iB.x, wv.y, h[16 + sub * 2 + 1]);
                    h[24 + sub * 2    ] = fma2(iB.y, wv.x, h[24 + sub * 2    ]);
                    h[24 + sub * 2 + 1] = fma2(iB.y, wv.y, h[24 + sub * 2 + 1]);
                }
            }

            // epilogue: relu -> dot w2 -> reduce over ag (lane bits 0-1) -> logits
            #pragma unroll
            for (int pp = 0; pp < 4; pp++) {
                float s0 = 0.f, s1 = 0.f;
                #pragma unroll
                for (int aa = 0; aa < 8; aa++) {
                    float u, v; up2(h[pp * 8 + aa], u, v);
                    s0 = fmaf(fmaxf(u, 0.f), w2s[a0 + aa], s0);
                    s1 = fmaf(fmaxf(v, 0.f), w2s[a0 + aa], s1);
                }
                s0 += __shfl_xor_sync(0xFFFFFFFFu, s0, 1);
                s0 += __shfl_xor_sync(0xFFFFFFFFu, s0, 2);
                s1 += __shfl_xor_sync(0xFFFFFFFFu, s1, 1);
                s1 += __shfl_xor_sync(0xFFFFFFFFu, s1, 2);
                if (ag == 0) {
                    int p = c * PC + pg * 4 + pp;       // lo pair (always < 2016)
                    lg[p] = b2v + s0;
                    int ph = p + 256;                    // hi pair
                    if (ph < NPAIR) lg[ph] = b2v + s1;
                }
            }
        }
        __syncthreads();
    }

    // ===================== softmax over 2016 pairs =========================
    float lmax = -3.402823466e+38f;
    for (int p = t; p < NPAIR; p += NTHREADS) lmax = fmaxf(lmax, lg[p]);
    #pragma unroll
    for (int o = 16; o > 0; o >>= 1) lmax = fmaxf(lmax, __shfl_xor_sync(0xFFFFFFFFu, lmax, o));
    if (lane == 0) red[warp] = lmax;
    __syncthreads();
    if (t == 0) {
        float m = red[0];
        #pragma unroll
        for (int w = 1; w < 8; w++) m = fmaxf(m, red[w]);
        red[0] = m;
    }
    __syncthreads();
    const float gmax = red[0];
    __syncthreads();

    float lsum = 0.f;
    for (int p = t; p < NPAIR; p += NTHREADS) {
        float ev = expf(lg[p] - gmax);
        lg[p] = ev;
        lsum += ev;
    }
    #pragma unroll
    for (int o = 16; o > 0; o >>= 1) lsum += __shfl_xor_sync(0xFFFFFFFFu, lsum, o);
    if (lane == 0) red[warp] = lsum;
    __syncthreads();
    if (t == 0) {
        float s = 0.f;
        #pragma unroll
        for (int w = 0; w < 8; w++) s += red[w];
        red[0] = 1.0f / s;
    }
    __syncthreads();
    const float inv = red[0];

    for (int p = t; p < NPAIR; p += NTHREADS) {
        float av = lg[p] * inv;
        lg[p] = av;
        if (attnP) attnP[(size_t)b * NPAIR + p] = av;
    }
    __syncthreads();

    // ===================== weighted sum over pairs (f32x2) =================
    if (outP) {
        ull acc2[EDIM / 2];
        #pragma unroll
        for (int e2 = 0; e2 < EDIM / 2; e2++) acc2[e2] = 0ull;

        for (int p = t; p < NPAIR; p += NTHREADS) {
            const unsigned short ij = ijp[p];
            const float* xi = xs + (ij >> 8) * XSTR;
            const float* xj = xs + (ij & 255) * XSTR;
            const float w = lg[p];
            const ull wd = pk2(w, w);
            #pragma unroll
            for (int e2 = 0; e2 < EDIM / 2; e2++) {
                ull a = *(const ull*)(xi + 2 * e2);
                ull bv = *(const ull*)(xj + 2 * e2);
                ull pr = fma2(a, bv, 0ull);            // a*b
                acc2[e2] = fma2(pr, wd, acc2[e2]);
            }
        }

        float acc[EDIM];
        #pragma unroll
        for (int e2 = 0; e2 < EDIM / 2; e2++) up2(acc2[e2], acc[2 * e2], acc[2 * e2 + 1]);

        #pragma unroll
        for (int e = 0; e < EDIM; e++) {
            #pragma unroll
            for (int o = 16; o > 0; o >>= 1)
                acc[e] += __shfl_xor_sync(0xFFFFFFFFu, acc[e], o);
        }
        if (lane == 0) {
            #pragma unroll
            for (int e = 0; e < EDIM; e++) outred[warp][e] = acc[e];
        }
        __syncthreads();
        if (t < EDIM) {
            float s = 0.f;
            #pragma unroll
            for (int w = 0; w < 8; w++) s += outred[w][t];
            outP[(size_t)b * EDIM + t] = s;
        }
    }
}

extern "C" void kernel_launch(void* const* d_in, const int* in_sizes, int n_in,
                              void* d_out, int out_size) {
    const float* x  = (const float*)d_in[0];
    const float* W1 = (const float*)d_in[1];
    const float* b1 = (const float*)d_in[2];
    const float* W2 = (const float*)d_in[3];
    const float* b2 = (const float*)d_in[4];

    const int B = in_sizes[0] / (NF * EDIM);

    float* outP  = (float*)d_out;
    float* attnP = (float*)d_out + (size_t)B * EDIM;
    if (out_size == B * NPAIR) {           // attn only
        attnP = (float*)d_out;
        outP  = nullptr;
    } else if (out_size == B * EDIM) {     // outputs only
        attnP = nullptr;
    }

    cudaFuncSetAttribute(afm_kernel, cudaFuncAttributeMaxDynamicSharedMemorySize, SMEM_DYN);
    afm_kernel<<<B, NTHREADS, SMEM_DYN>>>(x, W1, b1, W2, b2, outP, attnP);
}

// round 4
// speedup vs baseline: 1.2857x; 1.2083x over previous
#include <cuda_runtime.h>
#include <cuda_bf16.h>
#include <cstdint>

// AFM layer: B=1024, N=64 fields, E=64, A=32, P = 2016 pairs.
//   inner[p,e] = x[i_p,e]*x[j_p,e]
//   h = relu(inner @ W1 + b1); logits = h @ W2 + b2
//   attn = softmax(logits over p); out[e] = sum_p inner[p,e]*attn[p]
// Pairs enumerated as 280 segments: (row i, 8-aligned j-block jb), j in [jb,jb+8),
// valid iff j > i. Inner formed in registers from xT — no materialized tile.

#define NF 64
#define EDIM 64
#define ADIM 32
#define NPAIR 2016
#define NSEG 280
#define XTSTR 68      // xT row stride (floats): 272B = 16B-aligned rows
#define XSTR 66       // xs row stride (floats): 264B = 8B-aligned rows
#define NTHREADS 256

typedef unsigned long long ull;

__device__ __forceinline__ ull pk2(float lo, float hi) {
    ull r; asm("mov.b64 %0, {%1, %2};" : "=l"(r) : "f"(lo), "f"(hi)); return r;
}
__device__ __forceinline__ void up2(ull v, float& lo, float& hi) {
    asm("mov.b64 {%0, %1}, %2;" : "=f"(lo), "=f"(hi) : "l"(v));
}
__device__ __forceinline__ ull fma2(ull a, ull b, ull c) {
    ull d; asm("fma.rn.f32x2 %0, %1, %2, %3;" : "=l"(d) : "l"(a), "l"(b), "l"(c)); return d;
}

// dynamic smem (bytes):
//   w1d  : ull[2048]          @ 0      (16384)  duplicated+swizzled W1
//   xT   : float[64*68]       @ 16384  (17408)  x transposed [e][f]
//   xs   : float[64*66]       @ 33792  (16896)  x row-major [f][e]
//   lg   : float[2016]        @ 50688  (8064)   logits -> attn
//   segt : uint[280]          @ 58752  (1120)   segment table
//   ijp  : ushort[2016]       @ 59904  (4032)   (i<<8|j)
#define OFF_W1   0
#define OFF_XT   16384
#define OFF_XS   33792
#define OFF_LG   50688
#define OFF_SEG  58752
#define OFF_IJP  59904
#define SMEM_DYN 64000

__global__ __launch_bounds__(NTHREADS, 2)
void afm_kernel(const float* __restrict__ x,    // (B, 64, 64)
                const float* __restrict__ W1,   // (64, 32)
                const float* __restrict__ b1,   // (32)
                const float* __restrict__ W2,   // (32, 1)
                const float* __restrict__ b2,   // (1)
                float* __restrict__ outP,       // (B, 64) or null
                float* __restrict__ attnP)      // (B, 2016) or null
{
    extern __shared__ char smx[];
    ull*            w1d  = (ull*)(smx + OFF_W1);
    float*          xT   = (float*)(smx + OFF_XT);
    float*          xs   = (float*)(smx + OFF_XS);
    float*          lg   = (float*)(smx + OFF_LG);
    unsigned*       segt = (unsigned*)(smx + OFF_SEG);
    unsigned short* ijp  = (unsigned short*)(smx + OFF_IJP);

    __shared__ float b1s[ADIM];
    __shared__ float w2s[ADIM];
    __shared__ float b2s;
    __shared__ float red[8];
    __shared__ float outred[8][EDIM];

    const int t    = threadIdx.x;
    const int lane = t & 31;
    const int warp = t >> 5;
    const int b    = blockIdx.x;

    // ---- x tile: both layouts ----
    const float* xb = x + (size_t)b * (NF * EDIM);
    for (int idx = t; idx < NF * EDIM; idx += NTHREADS) {
        int f = idx >> 6, e = idx & 63;
        float v = xb[idx];
        xs[f * XSTR + e] = v;
        xT[e * XTSTR + f] = v;
    }
    // ---- duplicated + swizzled W1 (ulonglong2 slot (e,sub,ag)) ----
    for (int idx = t; idx < EDIM * ADIM; idx += NTHREADS) {
        int e = idx >> 5, a = idx & 31;
        int ag = a >> 3, wi = a & 7, sub = wi >> 1, half = wi & 1;
        float w = W1[idx];
        w1d[(e * 16 + sub * 4 + ag) * 2 + half] = pk2(w, w);
    }
    if (t < ADIM) { b1s[t] = b1[t]; w2s[t] = W2[t]; }
    if (t == 0)   { b2s = b2[0]; }
    // ---- segment table + pair table ----
    if (t < NF - 1) {
        int i = t;
        // segstart(i) = 8*i - sum_{k=1..i} floor(k/8)
        int q = i >> 3;
        int sum = 4 * q * (q - 1) + (i - 8 * q + 1) * q;
        int segstart = 8 * i - sum;
        int jb0 = ((i + 1) >> 3) << 3;         // first 8-aligned block
        int nseg = 8 - ((i + 1) >> 3);
        int offi = i * 63 - (i * (i - 1)) / 2; // pair base of row i
        for (int s = 0; s < nseg; s++)
            segt[segstart + s] = (unsigned)i | ((unsigned)((jb0 >> 3) + s) << 6)
                               | ((unsigned)offi << 12);
        // ijp for phase 3
        for (int k = 0; k < NF - 1 - i; k++)
            ijp[offi + k] = (unsigned short)((i << 8) | (i + 1 + k));
    }
    __syncthreads();

    const float b2v = b2s;
    const int ag = t & 3;        // a-group (lane bits 0-1 -> shfl reduce)
    const int pg = t >> 2;       // segment slot 0..63 per pass
    const int a0 = ag * 8;
    const ulonglong2* wbase = ((const ulonglong2*)w1d) + ag;

    // ===================== GEMM: 5 passes x 64 segments ====================
    for (int pass = 0; pass < 5; pass++) {
        const int sidx = pg + (pass << 6);
        if (sidx < NSEG) {
            const unsigned sv = segt[sidx];
            const int i    = sv & 63;
            const int jb   = ((sv >> 6) & 63) << 3;
            const int offi = sv >> 12;

            ull h[32];
            #pragma unroll
            for (int aa = 0; aa < 8; aa++) {
                ull bb = pk2(b1s[a0 + aa], b1s[a0 + aa]);
                h[aa] = bb; h[8 + aa] = bb; h[16 + aa] = bb; h[24 + aa] = bb;
            }

            const float* xrow = xT + jb;
            const float* xirow = xT + i;
            #pragma unroll 4
            for (int e = 0; e < EDIM; e++) {
                const ulonglong2 A = *(const ulonglong2*)(xrow + e * XTSTR);
                const ulonglong2 Bv = *(const ulonglong2*)(xrow + e * XTSTR + 4);
                const float xi = xirow[e * XTSTR];
                const ull xi2 = pk2(xi, xi);
                const ull j0 = fma2(A.x,  xi2, 0ull);
                const ull j1 = fma2(A.y,  xi2, 0ull);
                const ull j2 = fma2(Bv.x, xi2, 0ull);
                const ull j3 = fma2(Bv.y, xi2, 0ull);
                const ulonglong2* wr = wbase + e * 16;
                #pragma unroll
                for (int sub = 0; sub < 4; sub++) {
                    const ulonglong2 wv = wr[sub * 4];
                    h[     sub * 2    ] = fma2(j0, wv.x, h[     sub * 2    ]);
                    h[     sub * 2 + 1] = fma2(j0, wv.y, h[     sub * 2 + 1]);
                    h[ 8 + sub * 2    ] = fma2(j1, wv.x, h[ 8 + sub * 2    ]);
                    h[ 8 + sub * 2 + 1] = fma2(j1, wv.y, h[ 8 + sub * 2 + 1]);
                    h[16 + sub * 2    ] = fma2(j2, wv.x, h[16 + sub * 2    ]);
                    h[16 + sub * 2 + 1] = fma2(j2, wv.y, h[16 + sub * 2 + 1]);
                    h[24 + sub * 2    ] = fma2(j3, wv.x, h[24 + sub * 2    ]);
                    h[24 + sub * 2 + 1] = fma2(j3, wv.y, h[24 + sub * 2 + 1]);
                }
            }

            // epilogue: relu -> dot w2 -> reduce over ag -> store valid logits
            #pragma unroll
            for (int pp = 0; pp < 4; pp++) {
                float s0 = 0.f, s1 = 0.f;
                #pragma unroll
                for (int aa = 0; aa < 8; aa++) {
                    float u, v; up2(h[pp * 8 + aa], u, v);
                    s0 = fmaf(fmaxf(u, 0.f), w2s[a0 + aa], s0);
                    s1 = fmaf(fmaxf(v, 0.f), w2s[a0 + aa], s1);
                }
                s0 += __shfl_xor_sync(0xFFFFFFFFu, s0, 1);
                s0 += __shfl_xor_sync(0xFFFFFFFFu, s0, 2);
                s1 += __shfl_xor_sync(0xFFFFFFFFu, s1, 1);
                s1 += __shfl_xor_sync(0xFFFFFFFFu, s1, 2);
                if (ag == 0) {
                    const int jlo = jb + 2 * pp;
                    const int jhi = jlo + 1;
                    if (jlo > i) lg[offi + jlo - i - 1] = b2v + s0;
                    if (jhi > i) lg[offi + jhi - i - 1] = b2v + s1;
                }
            }
        }
    }
    __syncthreads();

    // ===================== softmax over 2016 pairs =========================
    float lmax = -3.402823466e+38f;
    for (int p = t; p < NPAIR; p += NTHREADS) lmax = fmaxf(lmax, lg[p]);
    #pragma unroll
    for (int o = 16; o > 0; o >>= 1) lmax = fmaxf(lmax, __shfl_xor_sync(0xFFFFFFFFu, lmax, o));
    if (lane == 0) red[warp] = lmax;
    __syncthreads();
    if (t == 0) {
        float m = red[0];
        #pragma unroll
        for (int w = 1; w < 8; w++) m = fmaxf(m, red[w]);
        red[0] = m;
    }
    __syncthreads();
    const float gmax = red[0];
    __syncthreads();

    float lsum = 0.f;
    for (int p = t; p < NPAIR; p += NTHREADS) {
        float ev = expf(lg[p] - gmax);
        lg[p] = ev;
        lsum += ev;
    }
    #pragma unroll
    for (int o = 16; o > 0; o >>= 1) lsum += __shfl_xor_sync(0xFFFFFFFFu, lsum, o);
    if (lane == 0) red[warp] = lsum;
    __syncthreads();
    if (t == 0) {
        float s = 0.f;
        #pragma unroll
        for (int w = 0; w < 8; w++) s += red[w];
        red[0] = 1.0f / s;
    }
    __syncthreads();
    const float inv = red[0];

    for (int p = t; p < NPAIR; p += NTHREADS) {
        float av = lg[p] * inv;
        lg[p] = av;
        if (attnP) attnP[(size_t)b * NPAIR + p] = av;
    }
    __syncthreads();

    // ===================== weighted sum over pairs (f32x2) =================
    if (outP) {
        ull acc2[EDIM / 2];
        #pragma unroll
        for (int e2 = 0; e2 < EDIM / 2; e2++) acc2[e2] = 0ull;

        for (int p = t; p < NPAIR; p += NTHREADS) {
            const unsigned short ij = ijp[p];
            const float* xi = xs + (ij >> 8) * XSTR;
            const float* xj = xs + (ij & 255) * XSTR;
            const float w = lg[p];
            const ull wd = pk2(w, w);
            #pragma unroll
            for (int e2 = 0; e2 < EDIM / 2; e2++) {
                ull a  = *(const ull*)(xi + 2 * e2);
                ull bv = *(const ull*)(xj + 2 * e2);
                ull pr = fma2(a, bv, 0ull);
                acc2[e2] = fma2(pr, wd, acc2[e2]);
            }
        }

        float acc[EDIM];
        #pragma unroll
        for (int e2 = 0; e2 < EDIM / 2; e2++) up2(acc2[e2], acc[2 * e2], acc[2 * e2 + 1]);

        #pragma unroll
        for (int e = 0; e < EDIM; e++) {
            #pragma unroll
            for (int o = 16; o > 0; o >>= 1)
                acc[e] += __shfl_xor_sync(0xFFFFFFFFu, acc[e], o);
        }
        if (lane == 0) {
            #pragma unroll
            for (int e = 0; e < EDIM; e++) outred[warp][e] = acc[e];
        }
        __syncthreads();
        if (t < EDIM) {
            float s = 0.f;
            #pragma unroll
            for (int w = 0; w < 8; w++) s += outred[w][t];
            outP[(size_t)b * EDIM + t] = s;
        }
    }
}

extern "C" void kernel_launch(void* const* d_in, const int* in_sizes, int n_in,
                              void* d_out, int out_size) {
    const float* x  = (const float*)d_in[0];
    const float* W1 = (const float*)d_in[1];
    const float* b1 = (const float*)d_in[2];
    const float* W2 = (const float*)d_in[3];
    const float* b2 = (const float*)d_in[4];

    const int B = in_sizes[0] / (NF * EDIM);

    float* outP  = (float*)d_out;
    float* attnP = (float*)d_out + (size_t)B * EDIM;
    if (out_size == B * NPAIR) {           // attn only
        attnP = (float*)d_out;
        outP  = nullptr;
    } else if (out_size == B * EDIM) {     // outputs only
        attnP = nullptr;
    }

    cudaFuncSetAttribute(afm_kernel, cudaFuncAttributeMaxDynamicSharedMemorySize, SMEM_DYN);
    afm_kernel<<<B, NTHREADS, SMEM_DYN>>>(x, W1, b1, W2, b2, outP, attnP);
}

// round 6
// speedup vs baseline: 1.7880x; 1.3906x over previous
#include <cuda_runtime.h>
#include <cuda_bf16.h>
#include <cstdint>

// AFM layer via mma.sync (sm_80-class HMMA, works on plain sm_100 target).
// B=1024, N=64 fields, E=64, A=32, P=2016 pairs (pad 2048).
//   inner[p,e] = x[i_p,e]*x[j_p,e]
//   h = relu(inner @ W1 + b1); logits = h @ W2 + b2
//   attn = softmax(logits); out[e] = sum_p inner[p,e]*attn[p]
// GEMM inner@W1: m16n8k16 bf16 mma with hi/lo split (Ah*Bh + Ah*Bl + Al*Bh),
// fp32 accum. A fragments built in registers straight from x tile.

#define NF 64
#define EDIM 64
#define ADIM 32
#define NPAIR 2016
#define XSTR 66
#define NTHREADS 256

typedef unsigned long long ull;

__device__ __forceinline__ ull pk2(float lo, float hi) {
    ull r; asm("mov.b64 %0, {%1, %2};" : "=l"(r) : "f"(lo), "f"(hi)); return r;
}
__device__ __forceinline__ void up2(ull v, float& lo, float& hi) {
    asm("mov.b64 {%0, %1}, %2;" : "=f"(lo), "=f"(hi) : "l"(v));
}
__device__ __forceinline__ ull fma2(ull a, ull b, ull c) {
    ull d; asm("fma.rn.f32x2 %0, %1, %2, %3;" : "=l"(d) : "l"(a), "l"(b), "l"(c)); return d;
}
// pack {vhi -> high16, vlo -> low16} as bf16x2
__device__ __forceinline__ uint32_t bf2(float vhi, float vlo) {
    uint32_t r; asm("cvt.rn.bf16x2.f32 %0, %1, %2;" : "=r"(r) : "f"(vhi), "f"(vlo)); return r;
}
// mma.sync m16n8k16 row.col bf16 -> f32
__device__ __forceinline__ void mma16816(float* c, uint32_t a0, uint32_t a1,
                                         uint32_t a2, uint32_t a3,
                                         uint32_t b0, uint32_t b1) {
    asm volatile(
        "mma.sync.aligned.m16n8k16.row.col.f32.bf16.bf16.f32 "
        "{%0,%1,%2,%3}, {%4,%5,%6,%7}, {%8,%9}, {%0,%1,%2,%3};"
        : "+f"(c[0]), "+f"(c[1]), "+f"(c[2]), "+f"(c[3])
        : "r"(a0), "r"(a1), "r"(a2), "r"(a3), "r"(b0), "r"(b1));
}
// split packed f32 pair into bf16x2 hi + f32x2 residual -> bf16x2 lo
__device__ __forceinline__ void split2(ull pr, uint32_t& hi, uint32_t& lo) {
    float v0, v1; up2(pr, v0, v1);
    hi = bf2(v1, v0);
    float h0 = __uint_as_float(hi << 16);
    float h1 = __uint_as_float(hi & 0xFFFF0000u);
    lo = bf2(v1 - h1, v0 - h0);
}

__global__ __launch_bounds__(NTHREADS, 2)
void afm_kernel(const float* __restrict__ x,    // (B, 64, 64)
                const float* __restrict__ W1,   // (64, 32)
                const float* __restrict__ b1,   // (32)
                const float* __restrict__ W2,   // (32, 1)
                const float* __restrict__ b2,   // (1)
                float* __restrict__ outP,       // (B, 64) or null
                float* __restrict__ attnP)      // (B, 2016) or null
{
    __shared__ float xs[NF * XSTR];              // 16896 B
    __shared__ uint32_t Wh[32 * 33];             // W1 hi bf16x2, [e2][a] stride 33
    __shared__ uint32_t Wl[32 * 33];             // W1 lo
    __shared__ float lg[2048];
    __shared__ unsigned short ijp[2048];
    __shared__ float b1s[ADIM];
    __shared__ float w2s[ADIM];
    __shared__ float b2ss;
    __shared__ float red[8];
    __shared__ float outred[8][EDIM];

    const int t    = threadIdx.x;
    const int lane = t & 31;
    const int warp = t >> 5;
    const int b    = blockIdx.x;

    // ---- x tile (coalesced in, stride-66 rows) ----
    const float* xb = x + (size_t)b * (NF * EDIM);
    for (int idx = t; idx < NF * EDIM; idx += NTHREADS) {
        int f = idx >> 6, e = idx & 63;
        xs[f * XSTR + e] = xb[idx];
    }
    // ---- W1 hi/lo bf16x2: word[e2][a] = {W1[2e2+1][a] hi, W1[2e2][a] lo} ----
    for (int idx = t; idx < 32 * 32; idx += NTHREADS) {
        int e2 = idx >> 5, a = idx & 31;
        float v0 = W1[(2 * e2) * ADIM + a];
        float v1 = W1[(2 * e2 + 1) * ADIM + a];
        uint32_t hi = bf2(v1, v0);
        float h0 = __uint_as_float(hi << 16);
        float h1 = __uint_as_float(hi & 0xFFFF0000u);
        Wh[e2 * 33 + a] = hi;
        Wl[e2 * 33 + a] = bf2(v1 - h1, v0 - h0);
    }
    if (t < ADIM) { b1s[t] = b1[t]; w2s[t] = W2[t]; }
    if (t == 0)   { b2ss = b2[0]; }
    // ---- pair table (pads 2016..2047 -> (0,0)) ----
    if (t < NF - 1) {
        int i = t;
        int offi = i * 63 - (i * (i - 1)) / 2;
        for (int k = 0; k < NF - 1 - i; k++)
            ijp[offi + k] = (unsigned short)((i << 8) | (i + 1 + k));
    }
    if (t >= 224) ijp[NPAIR + (t - 224)] = 0;
    __syncthreads();

    const float b2v = b2ss;
    const int tg = lane & 3;         // threadID in quad
    const int gr = lane >> 2;        // group id (row within tile)

    // ---- hoist B-hi fragments (32 regs) + b1/w2 epilogue constants ----
    uint32_t bh0[4][4], bh1[4][4];
    #pragma unroll
    for (int kb = 0; kb < 4; kb++) {
        #pragma unroll
        for (int nb = 0; nb < 4; nb++) {
            int e2 = kb * 8 + tg;
            int a  = nb * 8 + gr;
            bh0[kb][nb] = Wh[e2 * 33 + a];
            bh1[kb][nb] = Wh[(e2 + 4) * 33 + a];
        }
    }
    float b1v0[4], b1v1[4], w2v0[4], w2v1[4];
    #pragma unroll
    for (int nb = 0; nb < 4; nb++) {
        int a = nb * 8 + tg * 2;
        b1v0[nb] = b1s[a];     b1v1[nb] = b1s[a + 1];
        w2v0[nb] = w2s[a];     w2v1[nb] = w2s[a + 1];
    }

    // ================= GEMM: 16 tiles of 16 pairs per warp =================
    for (int tt = 0; tt < 16; tt++) {
        const int tbase = warp * 256 + tt * 16;
        const int p0 = tbase + gr;         // row gr
        const int p1 = p0 + 8;             // row gr+8
        const unsigned short ij0 = ijp[p0];
        const unsigned short ij1 = ijp[p1];
        const float* xi0 = xs + (ij0 >> 8) * XSTR;
        const float* xj0 = xs + (ij0 & 255) * XSTR;
        const float* xi1 = xs + (ij1 >> 8) * XSTR;
        const float* xj1 = xs + (ij1 & 255) * XSTR;

        float c[4][4];
        #pragma unroll
        for (int nb = 0; nb < 4; nb++)
            c[nb][0] = c[nb][1] = c[nb][2] = c[nb][3] = 0.f;

        #pragma unroll
        for (int kb = 0; kb < 4; kb++) {
            const int off = kb * 16 + tg * 2;
            // products: row gr cols {off,off+1} and {off+8,off+9}; same for row gr+8
            ull prA = fma2(*(const ull*)(xi0 + off),     *(const ull*)(xj0 + off),     0ull);
            ull prB = fma2(*(const ull*)(xi0 + off + 8), *(const ull*)(xj0 + off + 8), 0ull);
            ull prC = fma2(*(const ull*)(xi1 + off),     *(const ull*)(xj1 + off),     0ull);
            ull prD = fma2(*(const ull*)(xi1 + off + 8), *(const ull*)(xj1 + off + 8), 0ull);
            uint32_t a0, a1, a2, a3, l0, l1, l2, l3;
            split2(prA, a0, l0);   // a0: row gr,   k off..off+1
            split2(prC, a1, l1);   // a1: row gr+8, k off..off+1
            split2(prB, a2, l2);   // a2: row gr,   k off+8..off+9
            split2(prD, a3, l3);   // a3: row gr+8, k off+8..off+9

            const int e2 = kb * 8 + tg;
            #pragma unroll
            for (int nb = 0; nb < 4; nb++) {
                const int a  = nb * 8 + gr;
                uint32_t bl0 = Wl[e2 * 33 + a];
                uint32_t bl1 = Wl[(e2 + 4) * 33 + a];
                mma16816(c[nb], a0, a1, a2, a3, bh0[kb][nb], bh1[kb][nb]); // Ah*Bh
                mma16816(c[nb], a0, a1, a2, a3, bl0, bl1);                 // Ah*Bl
                mma16816(c[nb], l0, l1, l2, l3, bh0[kb][nb], bh1[kb][nb]); // Al*Bh
            }
        }

        // epilogue: relu(+b1) dot w2, reduce across quad, write logits
        float s_lo = 0.f, s_hi = 0.f;
        #pragma unroll
        for (int nb = 0; nb < 4; nb++) {
            s_lo = fmaf(fmaxf(c[nb][0] + b1v0[nb], 0.f), w2v0[nb], s_lo);
            s_lo = fmaf(fmaxf(c[nb][1] + b1v1[nb], 0.f), w2v1[nb], s_lo);
            s_hi = fmaf(fmaxf(c[nb][2] + b1v0[nb], 0.f), w2v0[nb], s_hi);
            s_hi = fmaf(fmaxf(c[nb][3] + b1v1[nb], 0.f), w2v1[nb], s_hi);
        }
        s_lo += __shfl_xor_sync(0xFFFFFFFFu, s_lo, 1);
        s_lo += __shfl_xor_sync(0xFFFFFFFFu, s_lo, 2);
        s_hi += __shfl_xor_sync(0xFFFFFFFFu, s_hi, 1);
        s_hi += __shfl_xor_sync(0xFFFFFFFFu, s_hi, 2);
        if (tg == 0) {
            if (p0 < NPAIR) lg[p0] = s_lo + b2v;
            if (p1 < NPAIR) lg[p1] = s_hi + b2v;
        }
    }
    __syncthreads();

    // ===================== softmax over 2016 pairs =========================
    float lmax = -3.402823466e+38f;
    for (int p = t; p < NPAIR; p += NTHREADS) lmax = fmaxf(lmax, lg[p]);
    #pragma unroll
    for (int o = 16; o > 0; o >>= 1) lmax = fmaxf(lmax, __shfl_xor_sync(0xFFFFFFFFu, lmax, o));
    if (lane == 0) red[warp] = lmax;
    __syncthreads();
    if (t == 0) {
        float m = red[0];
        #pragma unroll
        for (int w = 1; w < 8; w++) m = fmaxf(m, red[w]);
        red[0] = m;
    }
    __syncthreads();
    const float gmax = red[0];
    __syncthreads();

    float lsum = 0.f;
    for (int p = t; p < NPAIR; p += NTHREADS) {
        float ev = expf(lg[p] - gmax);
        lg[p] = ev;
        lsum += ev;
    }
    #pragma unroll
    for (int o = 16; o > 0; o >>= 1) lsum += __shfl_xor_sync(0xFFFFFFFFu, lsum, o);
    if (lane == 0) red[warp] = lsum;
    __syncthreads();
    if (t == 0) {
        float s = 0.f;
        #pragma unroll
        for (int w = 0; w < 8; w++) s += red[w];
        red[0] = 1.0f / s;
    }
    __syncthreads();
    const float inv = red[0];

    for (int p = t; p < NPAIR; p += NTHREADS) {
        float av = lg[p] * inv;
        lg[p] = av;
        if (attnP) attnP[(size_t)b * NPAIR + p] = av;
    }
    __syncthreads();

    // ===================== weighted sum over pairs (f32x2) =================
    if (outP) {
        ull acc2[EDIM / 2];
        #pragma unroll
        for (int e2 = 0; e2 < EDIM / 2; e2++) acc2[e2] = 0ull;

        for (int p = t; p < NPAIR; p += NTHREADS) {
            const unsigned short ij = ijp[p];
            const float* xi = xs + (ij >> 8) * XSTR;
            const float* xj = xs + (ij & 255) * XSTR;
            const float w = lg[p];
            const ull wd = pk2(w, w);
            #pragma unroll
            for (int e2 = 0; e2 < EDIM / 2; e2++) {
                ull a  = *(const ull*)(xi + 2 * e2);
                ull bv = *(const ull*)(xj + 2 * e2);
                ull pr = fma2(a, bv, 0ull);
                acc2[e2] = fma2(pr, wd, acc2[e2]);
            }
        }

        float acc[EDIM];
        #pragma unroll
        for (int e2 = 0; e2 < EDIM / 2; e2++) up2(acc2[e2], acc[2 * e2], acc[2 * e2 + 1]);

        #pragma unroll
        for (int e = 0; e < EDIM; e++) {
            #pragma unroll
            for (int o = 16; o > 0; o >>= 1)
                acc[e] += __shfl_xor_sync(0xFFFFFFFFu, acc[e], o);
        }
        if (lane == 0) {
            #pragma unroll
            for (int e = 0; e < EDIM; e++) outred[warp][e] = acc[e];
        }
        __syncthreads();
        if (t < EDIM) {
            float s = 0.f;
            #pragma unroll
            for (int w = 0; w < 8; w++) s += outred[w][t];
            outP[(size_t)b * EDIM + t] = s;
        }
    }
}

extern "C" void kernel_launch(void* const* d_in, const int* in_sizes, int n_in,
                              void* d_out, int out_size) {
    const float* x  = (const float*)d_in[0];
    const float* W1 = (const float*)d_in[1];
    const float* b1 = (const float*)d_in[2];
    const float* W2 = (const float*)d_in[3];
    const float* b2 = (const float*)d_in[4];

    const int B = in_sizes[0] / (NF * EDIM);

    float* outP  = (float*)d_out;
    float* attnP = (float*)d_out + (size_t)B * EDIM;
    if (out_size == B * NPAIR) {           // attn only
        attnP = (float*)d_out;
        outP  = nullptr;
    } else if (out_size == B * EDIM) {     // outputs only
        attnP = nullptr;
    }

    afm_kernel<<<B, NTHREADS>>>(x, W1, b1, W2, b2, outP, attnP);
}

// round 7
// speedup vs baseline: 2.7573x; 1.5421x over previous
#include <cuda_runtime.h>
#include <cuda_bf16.h>
#include <cstdint>

// AFM layer via mma.sync (sm_80-class HMMA on sm_100 target).
// B=1024, N=64 fields, E=64, A=32, P=2016 pairs (pad 2048).
//   Phase 1: logits = relu(inner@W1 + b1)@W2 + b2 via m16n8k16 bf16 hi/lo mma.
//   Phase 2: softmax over 2016.
//   Phase 3: out = 0.5 * colsum( x .* (W@x) ), W = symmetrized attn, via mma.

#define NF 64
#define EDIM 64
#define ADIM 32
#define NPAIR 2016
#define XSTR 66
#define XPS 72         // Xp stride (words): tg*8+gr -> conflict-free
#define WPS 44         // Wp stride (words): gr*12+tg -> conflict-free
#define NTHREADS 256

// dynamic smem layout (bytes)
#define OFF_XS   0          // float[64*66]  = 16896
#define OFF_W1H  16896      // u32[32*33]    = 4224
#define OFF_W1L  21120      // u32[32*33]    = 4224
#define OFF_LG   25344      // float[2048]   = 8192
#define OFF_IJP  33536      // u16[2048]     = 4096
#define OFF_XPH  37632      // u32[32*72]    = 9216
#define OFF_XPL  46848      // u32[32*72]    = 9216
#define OFF_WPH  56064      // u32[64*44]    = 11264
#define OFF_WPL  67328      // u32[64*44]    = 11264
#define OFF_MISC 78592      // b1s[32] w2s[32] red[8] b2
#define SMEM_DYN 78912

typedef unsigned long long ull;

__device__ __forceinline__ ull pk2(float lo, float hi) {
    ull r; asm("mov.b64 %0, {%1, %2};" : "=l"(r) : "f"(lo), "f"(hi)); return r;
}
__device__ __forceinline__ void up2(ull v, float& lo, float& hi) {
    asm("mov.b64 {%0, %1}, %2;" : "=f"(lo), "=f"(hi) : "l"(v));
}
__device__ __forceinline__ ull fma2(ull a, ull b, ull c) {
    ull d; asm("fma.rn.f32x2 %0, %1, %2, %3;" : "=l"(d) : "l"(a), "l"(b), "l"(c)); return d;
}
__device__ __forceinline__ uint32_t bf2(float vhi, float vlo) {
    uint32_t r; asm("cvt.rn.bf16x2.f32 %0, %1, %2;" : "=r"(r) : "f"(vhi), "f"(vlo)); return r;
}
__device__ __forceinline__ void mma16816(float* c, uint32_t a0, uint32_t a1,
                                         uint32_t a2, uint32_t a3,
                                         uint32_t b0, uint32_t b1) {
    asm volatile(
        "mma.sync.aligned.m16n8k16.row.col.f32.bf16.bf16.f32 "
        "{%0,%1,%2,%3}, {%4,%5,%6,%7}, {%8,%9}, {%0,%1,%2,%3};"
        : "+f"(c[0]), "+f"(c[1]), "+f"(c[2]), "+f"(c[3])
        : "r"(a0), "r"(a1), "r"(a2), "r"(a3), "r"(b0), "r"(b1));
}
__device__ __forceinline__ void split2(ull pr, uint32_t& hi, uint32_t& lo) {
    float v0, v1; up2(pr, v0, v1);
    hi = bf2(v1, v0);
    float h0 = __uint_as_float(hi << 16);
    float h1 = __uint_as_float(hi & 0xFFFF0000u);
    lo = bf2(v1 - h1, v0 - h0);
}

__global__ __launch_bounds__(NTHREADS, 2)
void afm_kernel(const float* __restrict__ x,    // (B, 64, 64)
                const float* __restrict__ W1,   // (64, 32)
                const float* __restrict__ b1,   // (32)
                const float* __restrict__ W2,   // (32, 1)
                const float* __restrict__ b2,   // (1)
                float* __restrict__ outP,       // (B, 64) or null
                float* __restrict__ attnP)      // (B, 2016) or null
{
    extern __shared__ char smx[];
    float*          xs   = (float*)(smx + OFF_XS);
    uint32_t*       W1h  = (uint32_t*)(smx + OFF_W1H);
    uint32_t*       W1l  = (uint32_t*)(smx + OFF_W1L);
    float*          lg   = (float*)(smx + OFF_LG);
    unsigned short* ijp  = (unsigned short*)(smx + OFF_IJP);
    uint32_t*       Xph  = (uint32_t*)(smx + OFF_XPH);
    uint32_t*       Xpl  = (uint32_t*)(smx + OFF_XPL);
    uint32_t*       Wph  = (uint32_t*)(smx + OFF_WPH);
    uint32_t*       Wpl  = (uint32_t*)(smx + OFF_WPL);
    uint16_t*       Wph16 = (uint16_t*)Wph;
    uint16_t*       Wpl16 = (uint16_t*)Wpl;
    float*          b1s  = (float*)(smx + OFF_MISC);
    float*          w2s  = b1s + 32;
    float*          red  = w2s + 32;
    float*          b2sp = red + 8;

    const int t    = threadIdx.x;
    const int lane = t & 31;
    const int warp = t >> 5;
    const int b    = blockIdx.x;

    // ======================= prologue ======================================
    const float* xb = x + (size_t)b * (NF * EDIM);
    for (int idx = t; idx < NF * EDIM; idx += NTHREADS) {
        int f = idx >> 6, e = idx & 63;
        xs[f * XSTR + e] = xb[idx];
    }
    // Xp: packed bf16x2 over field pairs: word[j2][e] = {x[2j2+1][e] hi, x[2j2][e] lo}
    for (int idx = t; idx < 32 * 64; idx += NTHREADS) {
        int j2 = idx >> 6, e = idx & 63;
        float v0 = xb[(2 * j2) * EDIM + e];
        float v1 = xb[(2 * j2 + 1) * EDIM + e];
        uint32_t hi = bf2(v1, v0);
        float h0 = __uint_as_float(hi << 16);
        float h1 = __uint_as_float(hi & 0xFFFF0000u);
        Xph[j2 * XPS + e] = hi;
        Xpl[j2 * XPS + e] = bf2(v1 - h1, v0 - h0);
    }
    // W1 hi/lo bf16x2: word[e2][a] = {W1[2e2+1][a] hi, W1[2e2][a] lo}
    for (int idx = t; idx < 32 * 32; idx += NTHREADS) {
        int e2 = idx >> 5, a = idx & 31;
        float v0 = W1[(2 * e2) * ADIM + a];
        float v1 = W1[(2 * e2 + 1) * ADIM + a];
        uint32_t hi = bf2(v1, v0);
        float h0 = __uint_as_float(hi << 16);
        float h1 = __uint_as_float(hi & 0xFFFF0000u);
        W1h[e2 * 33 + a] = hi;
        W1l[e2 * 33 + a] = bf2(v1 - h1, v0 - h0);
    }
    // zero attn matrices
    for (int idx = t; idx < 64 * WPS; idx += NTHREADS) {
        Wph[idx] = 0u;
        Wpl[idx] = 0u;
    }
    if (t < ADIM) { b1s[t] = b1[t]; w2s[t] = W2[t]; }
    if (t == 0)   { b2sp[0] = b2[0]; }
    if (t < NF - 1) {
        int i = t;
        int offi = i * 63 - (i * (i - 1)) / 2;
        for (int k = 0; k < NF - 1 - i; k++)
            ijp[offi + k] = (unsigned short)((i << 8) | (i + 1 + k));
    }
    if (t >= 224) ijp[NPAIR + (t - 224)] = 0;
    __syncthreads();

    const float b2v = b2sp[0];
    const int tg = lane & 3;
    const int gr = lane >> 2;

    // hoisted B fragments (hi+lo) + epilogue constants
    uint32_t bh0[4][4], bh1[4][4], bl0[4][4], bl1[4][4];
    #pragma unroll
    for (int kb = 0; kb < 4; kb++) {
        #pragma unroll
        for (int nb = 0; nb < 4; nb++) {
            int e2 = kb * 8 + tg;
            int a  = nb * 8 + gr;
            bh0[kb][nb] = W1h[e2 * 33 + a];
            bh1[kb][nb] = W1h[(e2 + 4) * 33 + a];
            bl0[kb][nb] = W1l[e2 * 33 + a];
            bl1[kb][nb] = W1l[(e2 + 4) * 33 + a];
        }
    }
    float b1v0[4], b1v1[4], w2v0[4], w2v1[4];
    #pragma unroll
    for (int nb = 0; nb < 4; nb++) {
        int a = nb * 8 + tg * 2;
        b1v0[nb] = b1s[a];     b1v1[nb] = b1s[a + 1];
        w2v0[nb] = w2s[a];     w2v1[nb] = w2s[a + 1];
    }

    // ================= Phase 1: logits via mma =============================
    for (int tt = 0; tt < 16; tt++) {
        const int p0 = warp * 256 + tt * 16 + gr;
        const int p1 = p0 + 8;
        const unsigned short ij0 = ijp[p0];
        const unsigned short ij1 = ijp[p1];
        const float* xi0 = xs + (ij0 >> 8) * XSTR;
        const float* xj0 = xs + (ij0 & 255) * XSTR;
        const float* xi1 = xs + (ij1 >> 8) * XSTR;
        const float* xj1 = xs + (ij1 & 255) * XSTR;

        float c[4][4];
        #pragma unroll
        for (int nb = 0; nb < 4; nb++)
            c[nb][0] = c[nb][1] = c[nb][2] = c[nb][3] = 0.f;

        #pragma unroll
        for (int kb = 0; kb < 4; kb++) {
            const int off = kb * 16 + tg * 2;
            ull prA = fma2(*(const ull*)(xi0 + off),     *(const ull*)(xj0 + off),     0ull);
            ull prB = fma2(*(const ull*)(xi0 + off + 8), *(const ull*)(xj0 + off + 8), 0ull);
            ull prC = fma2(*(const ull*)(xi1 + off),     *(const ull*)(xj1 + off),     0ull);
            ull prD = fma2(*(const ull*)(xi1 + off + 8), *(const ull*)(xj1 + off + 8), 0ull);
            uint32_t a0, a1, a2, a3, l0, l1, l2, l3;
            split2(prA, a0, l0);
            split2(prC, a1, l1);
            split2(prB, a2, l2);
            split2(prD, a3, l3);
            #pragma unroll
            for (int nb = 0; nb < 4; nb++) {
                mma16816(c[nb], a0, a1, a2, a3, bh0[kb][nb], bh1[kb][nb]);
                mma16816(c[nb], a0, a1, a2, a3, bl0[kb][nb], bl1[kb][nb]);
                mma16816(c[nb], l0, l1, l2, l3, bh0[kb][nb], bh1[kb][nb]);
            }
        }

        float s_lo = 0.f, s_hi = 0.f;
        #pragma unroll
        for (int nb = 0; nb < 4; nb++) {
            s_lo = fmaf(fmaxf(c[nb][0] + b1v0[nb], 0.f), w2v0[nb], s_lo);
            s_lo = fmaf(fmaxf(c[nb][1] + b1v1[nb], 0.f), w2v1[nb], s_lo);
            s_hi = fmaf(fmaxf(c[nb][2] + b1v0[nb], 0.f), w2v0[nb], s_hi);
            s_hi = fmaf(fmaxf(c[nb][3] + b1v1[nb], 0.f), w2v1[nb], s_hi);
        }
        s_lo += __shfl_xor_sync(0xFFFFFFFFu, s_lo, 1);
        s_lo += __shfl_xor_sync(0xFFFFFFFFu, s_lo, 2);
        s_hi += __shfl_xor_sync(0xFFFFFFFFu, s_hi, 1);
        s_hi += __shfl_xor_sync(0xFFFFFFFFu, s_hi, 2);
        if (tg == 0) {
            if (p0 < NPAIR) lg[p0] = s_lo + b2v;
            if (p1 < NPAIR) lg[p1] = s_hi + b2v;
        }
    }
    __syncthreads();

    // ================= Phase 2: softmax ====================================
    float lmax = -3.402823466e+38f;
    for (int p = t; p < NPAIR; p += NTHREADS) lmax = fmaxf(lmax, lg[p]);
    #pragma unroll
    for (int o = 16; o > 0; o >>= 1) lmax = fmaxf(lmax, __shfl_xor_sync(0xFFFFFFFFu, lmax, o));
    if (lane == 0) red[warp] = lmax;
    __syncthreads();
    if (t == 0) {
        float m = red[0];
        #pragma unroll
        for (int w = 1; w < 8; w++) m = fmaxf(m, red[w]);
        red[0] = m;
    }
    __syncthreads();
    const float gmax = red[0];
    __syncthreads();

    float lsum = 0.f;
    for (int p = t; p < NPAIR; p += NTHREADS) {
        float ev = expf(lg[p] - gmax);
        lg[p] = ev;
        lsum += ev;
    }
    #pragma unroll
    for (int o = 16; o > 0; o >>= 1) lsum += __shfl_xor_sync(0xFFFFFFFFu, lsum, o);
    if (lane == 0) red[warp] = lsum;
    __syncthreads();
    if (t == 0) {
        float s = 0.f;
        #pragma unroll
        for (int w = 0; w < 8; w++) s += red[w];
        red[0] = 1.0f / s;
    }
    __syncthreads();
    const float inv = red[0];

    // normalize + emit attn + scatter symmetric W (bf16 hi/lo)
    for (int p = t; p < NPAIR; p += NTHREADS) {
        float av = lg[p] * inv;
        if (attnP) attnP[(size_t)b * NPAIR + p] = av;
        const unsigned short ij = ijp[p];
        const int i = ij >> 8, j = ij & 255;
        uint32_t hpair = bf2(0.f, av);              // low half = bf16(av)
        uint16_t hb = (uint16_t)(hpair & 0xFFFFu);
        float hv = __uint_as_float((uint32_t)hb << 16);
        uint32_t lpair = bf2(0.f, av - hv);
        uint16_t lb = (uint16_t)(lpair & 0xFFFFu);
        Wph16[i * (2 * WPS) + j] = hb;
        Wph16[j * (2 * WPS) + i] = hb;
        Wpl16[i * (2 * WPS) + j] = lb;
        Wpl16[j * (2 * WPS) + i] = lb;
    }
    __syncthreads();

    // ================= Phase 3: out = 0.5 * colsum(x .* (W@x)) =============
    if (outP) {
        float c[4][4];
        #pragma unroll
        for (int m = 0; m < 4; m++)
            c[m][0] = c[m][1] = c[m][2] = c[m][3] = 0.f;

        const int ecol = warp * 8 + gr;   // B-fragment column (n = e)
        #pragma unroll
        for (int kb = 0; kb < 4; kb++) {
            const int j2a = kb * 8 + tg;
            uint32_t xh0 = Xph[j2a * XPS + ecol];
            uint32_t xh1 = Xph[(j2a + 4) * XPS + ecol];
            uint32_t xl0 = Xpl[j2a * XPS + ecol];
            uint32_t xl1 = Xpl[(j2a + 4) * XPS + ecol];
            #pragma unroll
            for (int m = 0; m < 4; m++) {
                const int r0 = (m * 16 + gr) * WPS;
                const int r1 = (m * 16 + gr + 8) * WPS;
                uint32_t ah0 = Wph[r0 + j2a];
                uint32_t ah1 = Wph[r1 + j2a];
                uint32_t ah2 = Wph[r0 + j2a + 4];
                uint32_t ah3 = Wph[r1 + j2a + 4];
                uint32_t al0 = Wpl[r0 + j2a];
                uint32_t al1 = Wpl[r1 + j2a];
                uint32_t al2 = Wpl[r0 + j2a + 4];
                uint32_t al3 = Wpl[r1 + j2a + 4];
                mma16816(c[m], ah0, ah1, ah2, ah3, xh0, xh1);   // Wh*Xh
                mma16816(c[m], ah0, ah1, ah2, ah3, xl0, xl1);   // Wh*Xl
                mma16816(c[m], al0, al1, al2, al3, xh0, xh1);   // Wl*Xh
            }
        }

        // contract with x and reduce over rows i
        const int e0 = warp * 8 + tg * 2;
        float pe0 = 0.f, pe1 = 0.f;
        #pragma unroll
        for (int m = 0; m < 4; m++) {
            const int i0 = m * 16 + gr;
            const int i1 = i0 + 8;
            float x00, x01, x10, x11;
            up2(*(const ull*)(xs + i0 * XSTR + e0), x00, x01);
            up2(*(const ull*)(xs + i1 * XSTR + e0), x10, x11);
            pe0 = fmaf(c[m][0], x00, pe0);
            pe1 = fmaf(c[m][1], x01, pe1);
            pe0 = fmaf(c[m][2], x10, pe0);
            pe1 = fmaf(c[m][3], x11, pe1);
        }
        #pragma unroll
        for (int o = 4; o < 32; o <<= 1) {
            pe0 += __shfl_xor_sync(0xFFFFFFFFu, pe0, o);
            pe1 += __shfl_xor_sync(0xFFFFFFFFu, pe1, o);
        }
        if (gr == 0) {
            outP[(size_t)b * EDIM + e0]     = 0.5f * pe0;
            outP[(size_t)b * EDIM + e0 + 1] = 0.5f * pe1;
        }
    }
}

extern "C" void kernel_launch(void* const* d_in, const int* in_sizes, int n_in,
                              void* d_out, int out_size) {
    const float* x  = (const float*)d_in[0];
    const float* W1 = (const float*)d_in[1];
    const float* b1 = (const float*)d_in[2];
    const float* W2 = (const float*)d_in[3];
    const float* b2 = (const float*)d_in[4];

    const int B = in_sizes[0] / (NF * EDIM);

    float* outP  = (float*)d_out;
    float* attnP = (float*)d_out + (size_t)B * EDIM;
    if (out_size == B * NPAIR) {           // attn only
        attnP = (float*)d_out;
        outP  = nullptr;
    } else if (out_size == B * EDIM) {     // outputs only
        attnP = nullptr;
    }

    cudaFuncSetAttribute(afm_kernel, cudaFuncAttributeMaxDynamicSharedMemorySize, SMEM_DYN);
    afm_kernel<<<B, NTHREADS, SMEM_DYN>>>(x, W1, b1, W2, b2, outP, attnP);
}

// round 8
// speedup vs baseline: 2.9744x; 1.0787x over previous
#include <cuda_runtime.h>
#include <cuda_bf16.h>
#include <cstdint>

// AFM layer via mma.sync (sm_80-class HMMA on sm_100 target).
// B=1024, N=64 fields, E=64, A=32, P=2016 pairs.
//   Phase 1: logits = relu(inner@W1 + b1)@W2 + b2 via m16n8k16 bf16 hi/lo mma,
//            pairs enumerated as 160 segments (row i, 16-aligned j-block):
//            xi loads broadcast, xj loads LDS.128 via permuted x layout.
//   Phase 2: softmax over 2016.
//   Phase 3: out = 0.5 * colsum( x .* (W@x) ), W = symmetrized attn, via mma.

#define NF 64
#define EDIM 64
#define ADIM 32
#define NPAIR 2016
#define XSTR 68        // permuted x row stride (words); 68/4 == 17 == 1 mod 8
#define XPS 72
#define WPS 44
#define NTHREADS 256
#define NSEGT 160      // 156 real segments + 4 pads

// dynamic smem layout (bytes)
#define OFF_XS   0          // float[64*68]  = 17408 (PERMUTED cols)
#define OFF_W1H  17408      // u32[32*33]    = 4224
#define OFF_W1L  21632      // u32[32*33]    = 4224
#define OFF_LG   25856      // float[2048]   = 8192
#define OFF_IJP  34048      // u16[2048]     = 4096
#define OFF_XPH  38144      // u32[32*72]    = 9216
#define OFF_XPL  47360      // u32[32*72]    = 9216
#define OFF_WPH  56576      // u32[64*44]    = 11264
#define OFF_WPL  67840      // u32[64*44]    = 11264
#define OFF_SEG  79104      // u32[160]      = 640
#define OFF_MISC 79744      // b1s[32] w2s[32] red[8] b2
#define SMEM_DYN 80064

typedef unsigned long long ull;

__device__ __forceinline__ ull pk2(float lo, float hi) {
    ull r; asm("mov.b64 %0, {%1, %2};" : "=l"(r) : "f"(lo), "f"(hi)); return r;
}
__device__ __forceinline__ void up2(ull v, float& lo, float& hi) {
    asm("mov.b64 {%0, %1}, %2;" : "=f"(lo), "=f"(hi) : "l"(v));
}
__device__ __forceinline__ ull fma2(ull a, ull b, ull c) {
    ull d; asm("fma.rn.f32x2 %0, %1, %2, %3;" : "=l"(d) : "l"(a), "l"(b), "l"(c)); return d;
}
__device__ __forceinline__ uint32_t bf2(float vhi, float vlo) {
    uint32_t r; asm("cvt.rn.bf16x2.f32 %0, %1, %2;" : "=r"(r) : "f"(vhi), "f"(vlo)); return r;
}
__device__ __forceinline__ void mma16816(float* c, uint32_t a0, uint32_t a1,
                                         uint32_t a2, uint32_t a3,
                                         uint32_t b0, uint32_t b1) {
    asm volatile(
        "mma.sync.aligned.m16n8k16.row.col.f32.bf16.bf16.f32 "
        "{%0,%1,%2,%3}, {%4,%5,%6,%7}, {%8,%9}, {%0,%1,%2,%3};"
        : "+f"(c[0]), "+f"(c[1]), "+f"(c[2]), "+f"(c[3])
        : "r"(a0), "r"(a1), "r"(a2), "r"(a3), "r"(b0), "r"(b1));
}
__device__ __forceinline__ void split2(ull pr, uint32_t& hi, uint32_t& lo) {
    float v0, v1; up2(pr, v0, v1);
    hi = bf2(v1, v0);
    float h0 = __uint_as_float(hi << 16);
    float h1 = __uint_as_float(hi & 0xFFFF0000u);
    lo = bf2(v1 - h1, v0 - h0);
}
// column permutation within a 16-block: [0,1,8,9, 2,3,10,11, 4,5,12,13, 6,7,14,15]
__device__ __forceinline__ int pcol(int e) {
    int w = e & 15;
    return (e & 48) + ((w >> 1) & 3) * 4 + (w & 1) + ((w >> 3) << 1);
}

__global__ __launch_bounds__(NTHREADS, 2)
void afm_kernel(const float* __restrict__ x,    // (B, 64, 64)
                const float* __restrict__ W1,   // (64, 32)
                const float* __restrict__ b1,   // (32)
                const float* __restrict__ W2,   // (32, 1)
                const float* __restrict__ b2,   // (1)
                float* __restrict__ outP,       // (B, 64) or null
                float* __restrict__ attnP)      // (B, 2016) or null
{
    extern __shared__ char smx[];
    float*          xs   = (float*)(smx + OFF_XS);      // permuted
    uint32_t*       W1h  = (uint32_t*)(smx + OFF_W1H);
    uint32_t*       W1l  = (uint32_t*)(smx + OFF_W1L);
    float*          lg   = (float*)(smx + OFF_LG);
    unsigned short* ijp  = (unsigned short*)(smx + OFF_IJP);
    uint32_t*       Xph  = (uint32_t*)(smx + OFF_XPH);
    uint32_t*       Xpl  = (uint32_t*)(smx + OFF_XPL);
    uint32_t*       Wph  = (uint32_t*)(smx + OFF_WPH);
    uint32_t*       Wpl  = (uint32_t*)(smx + OFF_WPL);
    uint32_t*       segt = (uint32_t*)(smx + OFF_SEG);
    uint16_t*       Wph16 = (uint16_t*)Wph;
    uint16_t*       Wpl16 = (uint16_t*)Wpl;
    float*          b1s  = (float*)(smx + OFF_MISC);
    float*          w2s  = b1s + 32;
    float*          red  = w2s + 32;
    float*          b2sp = red + 8;

    const int t    = threadIdx.x;
    const int lane = t & 31;
    const int warp = t >> 5;
    const int b    = blockIdx.x;

    // ======================= prologue ======================================
    const float* xb = x + (size_t)b * (NF * EDIM);
    for (int idx = t; idx < NF * EDIM; idx += NTHREADS) {
        int f = idx >> 6, e = idx & 63;
        xs[f * XSTR + pcol(e)] = xb[idx];
    }
    // Xp: packed bf16x2 over field pairs: word[j2][e] = {x[2j2+1][e], x[2j2][e]}
    for (int idx = t; idx < 32 * 64; idx += NTHREADS) {
        int j2 = idx >> 6, e = idx & 63;
        float v0 = xb[(2 * j2) * EDIM + e];
        float v1 = xb[(2 * j2 + 1) * EDIM + e];
        uint32_t hi = bf2(v1, v0);
        float h0 = __uint_as_float(hi << 16);
        float h1 = __uint_as_float(hi & 0xFFFF0000u);
        Xph[j2 * XPS + e] = hi;
        Xpl[j2 * XPS + e] = bf2(v1 - h1, v0 - h0);
    }
    // W1 hi/lo bf16x2: word[e2][a] = {W1[2e2+1][a], W1[2e2][a]}
    for (int idx = t; idx < 32 * 32; idx += NTHREADS) {
        int e2 = idx >> 5, a = idx & 31;
        float v0 = W1[(2 * e2) * ADIM + a];
        float v1 = W1[(2 * e2 + 1) * ADIM + a];
        uint32_t hi = bf2(v1, v0);
        float h0 = __uint_as_float(hi << 16);
        float h1 = __uint_as_float(hi & 0xFFFF0000u);
        W1h[e2 * 33 + a] = hi;
        W1l[e2 * 33 + a] = bf2(v1 - h1, v0 - h0);
    }
    // zero attn matrices
    for (int idx = t; idx < 64 * WPS; idx += NTHREADS) {
        Wph[idx] = 0u;
        Wpl[idx] = 0u;
    }
    if (t < ADIM) { b1s[t] = b1[t]; w2s[t] = W2[t]; }
    if (t == 0)   { b2sp[0] = b2[0]; }
    // pair table (phase 2/3 scatter) + segment table (phase 1)
    if (t < NF - 1) {
        int i = t;
        int offi = i * 63 - (i * (i - 1)) / 2;
        for (int k = 0; k < NF - 1 - i; k++)
            ijp[offi + k] = (unsigned short)((i << 8) | (i + 1 + k));
        // segbase(i) = 4i - S(i), S(i) = sum_{m=1..i} (m>>4)
        int q = i >> 4, r = i & 15;
        int S = 16 * (q * (q - 1) / 2) + q * (r + 1);
        int segbase = 4 * i - S;
        int first = (i + 1) >> 4;
        for (int s = first; s < 4; s++)
            segt[segbase + (s - first)] =
                (uint32_t)i | ((uint32_t)s << 6) | ((uint32_t)offi << 8);
    }
    if (t == 63) {   // pads 156..159: i=63 -> no j>i, all stores masked
        for (int s = 0; s < 4; s++) segt[156 + s] = 63u | (3u << 6);
    }
    if (t >= 224) ijp[NPAIR + (t - 224)] = 0;
    __syncthreads();

    const float b2v = b2sp[0];
    const int tg = lane & 3;
    const int gr = lane >> 2;

    // hoisted B fragments (hi+lo) + epilogue constants
    uint32_t bh0[4][4], bh1[4][4], bl0[4][4], bl1[4][4];
    #pragma unroll
    for (int kb = 0; kb < 4; kb++) {
        #pragma unroll
        for (int nb = 0; nb < 4; nb++) {
            int e2 = kb * 8 + tg;
            int a  = nb * 8 + gr;
            bh0[kb][nb] = W1h[e2 * 33 + a];
            bh1[kb][nb] = W1h[(e2 + 4) * 33 + a];
            bl0[kb][nb] = W1l[e2 * 33 + a];
            bl1[kb][nb] = W1l[(e2 + 4) * 33 + a];
        }
    }
    float b1v0[4], b1v1[4], w2v0[4], w2v1[4];
    #pragma unroll
    for (int nb = 0; nb < 4; nb++) {
        int a = nb * 8 + tg * 2;
        b1v0[nb] = b1s[a];     b1v1[nb] = b1s[a + 1];
        w2v0[nb] = w2s[a];     w2v1[nb] = w2s[a + 1];
    }

    // ================= Phase 1: logits via mma (segments) ==================
    for (int tt = 0; tt < NSEGT / 8; tt++) {
        const uint32_t sv = segt[tt * 8 + warp];
        const int i    = sv & 63;
        const int jb   = ((sv >> 6) & 3) << 4;
        const int offi = sv >> 8;

        const ulonglong2* xiP  = (const ulonglong2*)(xs + i * XSTR) + tg;
        const ulonglong2* xj0P = (const ulonglong2*)(xs + (jb + gr) * XSTR) + tg;
        const ulonglong2* xj1P = (const ulonglong2*)(xs + (jb + gr + 8) * XSTR) + tg;

        float c[4][4];
        #pragma unroll
        for (int nb = 0; nb < 4; nb++)
            c[nb][0] = c[nb][1] = c[nb][2] = c[nb][3] = 0.f;

        #pragma unroll
        for (int kb = 0; kb < 4; kb++) {
            // 16B loads: .x = cols {2tg,2tg+1}, .y = cols {2tg+8,2tg+9} (permuted)
            const ulonglong2 xiv = xiP[kb * 4];        // broadcast (same i all lanes of quad-col)
            const ulonglong2 xj0 = xj0P[kb * 4];       // row gr
            const ulonglong2 xj1 = xj1P[kb * 4];       // row gr+8
            ull prA = fma2(xj0.x, xiv.x, 0ull);        // row gr,   k low
            ull prB = fma2(xj0.y, xiv.y, 0ull);        // row gr,   k high
            ull prC = fma2(xj1.x, xiv.x, 0ull);        // row gr+8, k low
            ull prD = fma2(xj1.y, xiv.y, 0ull);        // row gr+8, k high
            uint32_t a0, a1, a2, a3, l0, l1, l2, l3;
            split2(prA, a0, l0);
            split2(prC, a1, l1);
            split2(prB, a2, l2);
            split2(prD, a3, l3);
            #pragma unroll
            for (int nb = 0; nb < 4; nb++) {
                mma16816(c[nb], a0, a1, a2, a3, bh0[kb][nb], bh1[kb][nb]);
                mma16816(c[nb], a0, a1, a2, a3, bl0[kb][nb], bl1[kb][nb]);
                mma16816(c[nb], l0, l1, l2, l3, bh0[kb][nb], bh1[kb][nb]);
            }
        }

        float s_lo = 0.f, s_hi = 0.f;
        #pragma unroll
        for (int nb = 0; nb < 4; nb++) {
            s_lo = fmaf(fmaxf(c[nb][0] + b1v0[nb], 0.f), w2v0[nb], s_lo);
            s_lo = fmaf(fmaxf(c[nb][1] + b1v1[nb], 0.f), w2v1[nb], s_lo);
            s_hi = fmaf(fmaxf(c[nb][2] + b1v0[nb], 0.f), w2v0[nb], s_hi);
            s_hi = fmaf(fmaxf(c[nb][3] + b1v1[nb], 0.f), w2v1[nb], s_hi);
        }
        s_lo += __shfl_xor_sync(0xFFFFFFFFu, s_lo, 1);
        s_lo += __shfl_xor_sync(0xFFFFFFFFu, s_lo, 2);
        s_hi += __shfl_xor_sync(0xFFFFFFFFu, s_hi, 1);
        s_hi += __shfl_xor_sync(0xFFFFFFFFu, s_hi, 2);
        if (tg == 0) {
            const int j0 = jb + gr;
            const int j1 = jb + gr + 8;
            if (j0 > i) lg[offi + j0 - i - 1] = s_lo + b2v;
            if (j1 > i) lg[offi + j1 - i - 1] = s_hi + b2v;
        }
    }
    __syncthreads();

    // ================= Phase 2: softmax ====================================
    float lmax = -3.402823466e+38f;
    for (int p = t; p < NPAIR; p += NTHREADS) lmax = fmaxf(lmax, lg[p]);
    #pragma unroll
    for (int o = 16; o > 0; o >>= 1) lmax = fmaxf(lmax, __shfl_xor_sync(0xFFFFFFFFu, lmax, o));
    if (lane == 0) red[warp] = lmax;
    __syncthreads();
    if (t == 0) {
        float m = red[0];
        #pragma unroll
        for (int w = 1; w < 8; w++) m = fmaxf(m, red[w]);
        red[0] = m;
    }
    __syncthreads();
    const float gmax = red[0];
    __syncthreads();

    float lsum = 0.f;
    for (int p = t; p < NPAIR; p += NTHREADS) {
        float ev = expf(lg[p] - gmax);
        lg[p] = ev;
        lsum += ev;
    }
    #pragma unroll
    for (int o = 16; o > 0; o >>= 1) lsum += __shfl_xor_sync(0xFFFFFFFFu, lsum, o);
    if (lane == 0) red[warp] = lsum;
    __syncthreads();
    if (t == 0) {
        float s = 0.f;
        #pragma unroll
        for (int w = 0; w < 8; w++) s += red[w];
        red[0] = 1.0f / s;
    }
    __syncthreads();
    const float inv = red[0];

    // normalize + emit attn + scatter symmetric W (bf16 hi/lo)
    for (int p = t; p < NPAIR; p += NTHREADS) {
        float av = lg[p] * inv;
        if (attnP) attnP[(size_t)b * NPAIR + p] = av;
        const unsigned short ij = ijp[p];
        const int i = ij >> 8, j = ij & 255;
        uint32_t hpair = bf2(0.f, av);
        uint16_t hb = (uint16_t)(hpair & 0xFFFFu);
        float hv = __uint_as_float((uint32_t)hb << 16);
        uint32_t lpair = bf2(0.f, av - hv);
        uint16_t lb = (uint16_t)(lpair & 0xFFFFu);
        Wph16[i * (2 * WPS) + j] = hb;
        Wph16[j * (2 * WPS) + i] = hb;
        Wpl16[i * (2 * WPS) + j] = lb;
        Wpl16[j * (2 * WPS) + i] = lb;
    }
    __syncthreads();

    // ================= Phase 3: out = 0.5 * colsum(x .* (W@x)) =============
    if (outP) {
        float c[4][4];
        #pragma unroll
        for (int m = 0; m < 4; m++)
            c[m][0] = c[m][1] = c[m][2] = c[m][3] = 0.f;

        const int ecol = warp * 8 + gr;
        #pragma unroll
        for (int kb = 0; kb < 4; kb++) {
            const int j2a = kb * 8 + tg;
            uint32_t xh0 = Xph[j2a * XPS + ecol];
            uint32_t xh1 = Xph[(j2a + 4) * XPS + ecol];
            uint32_t xl0 = Xpl[j2a * XPS + ecol];
            uint32_t xl1 = Xpl[(j2a + 4) * XPS + ecol];
            #pragma unroll
            for (int m = 0; m < 4; m++) {
                const int r0 = (m * 16 + gr) * WPS;
                const int r1 = (m * 16 + gr + 8) * WPS;
                uint32_t ah0 = Wph[r0 + j2a];
                uint32_t ah1 = Wph[r1 + j2a];
                uint32_t ah2 = Wph[r0 + j2a + 4];
                uint32_t ah3 = Wph[r1 + j2a + 4];
                uint32_t al0 = Wpl[r0 + j2a];
                uint32_t al1 = Wpl[r1 + j2a];
                uint32_t al2 = Wpl[r0 + j2a + 4];
                uint32_t al3 = Wpl[r1 + j2a + 4];
                mma16816(c[m], ah0, ah1, ah2, ah3, xh0, xh1);
                mma16816(c[m], ah0, ah1, ah2, ah3, xl0, xl1);
                mma16816(c[m], al0, al1, al2, al3, xh0, xh1);
            }
        }

        // contract with x (through permuted layout) and reduce over rows i
        const int e0 = warp * 8 + tg * 2;
        const int pe = pcol(e0);          // e0 even -> (e0, e0+1) contiguous
        float pe0 = 0.f, pe1 = 0.f;
        #pragma unroll
        for (int m = 0; m < 4; m++) {
            const int i0 = m * 16 + gr;
            const int i1 = i0 + 8;
            float x00, x01, x10, x11;
            up2(*(const ull*)(xs + i0 * XSTR + pe), x00, x01);
            up2(*(const ull*)(xs + i1 * XSTR + pe), x10, x11);
            pe0 = fmaf(c[m][0], x00, pe0);
            pe1 = fmaf(c[m][1], x01, pe1);
            pe0 = fmaf(c[m][2], x10, pe0);
            pe1 = fmaf(c[m][3], x11, pe1);
        }
        #pragma unroll
        for (int o = 4; o < 32; o <<= 1) {
            pe0 += __shfl_xor_sync(0xFFFFFFFFu, pe0, o);
            pe1 += __shfl_xor_sync(0xFFFFFFFFu, pe1, o);
        }
        if (gr == 0) {
            outP[(size_t)b * EDIM + e0]     = 0.5f * pe0;
            outP[(size_t)b * EDIM + e0 + 1] = 0.5f * pe1;
        }
    }
}

extern "C" void kernel_launch(void* const* d_in, const int* in_sizes, int n_in,
                              void* d_out, int out_size) {
    const float* x  = (const float*)d_in[0];
    const float* W1 = (const float*)d_in[1];
    const float* b1 = (const float*)d_in[2];
    const float* W2 = (const float*)d_in[3];
    const float* b2 = (const float*)d_in[4];

    const int B = in_sizes[0] / (NF * EDIM);

    float* outP  = (float*)d_out;
    float* attnP = (float*)d_out + (size_t)B * EDIM;
    if (out_size == B * NPAIR) {           // attn only
        attnP = (float*)d_out;
        outP  = nullptr;
    } else if (out_size == B * EDIM) {     // outputs only
        attnP = nullptr;
    }

    cudaFuncSetAttribute(afm_kernel, cudaFuncAttributeMaxDynamicSharedMemorySize, SMEM_DYN);
    afm_kernel<<<B, NTHREADS, SMEM_DYN>>>(x, W1, b1, W2, b2, outP, attnP);
}

// round 9
// speedup vs baseline: 3.0995x; 1.0421x over previous
#include <cuda_runtime.h>
#include <cuda_bf16.h>
#include <cuda_fp16.h>
#include <cstdint>

// AFM layer via mma.sync (sm_80-class HMMA on sm_100 target).
// B=1024, N=64 fields, E=64, A=32, P=2016 pairs.
//   Phase 1: logits = relu(inner@W1 + b1)@W2 + b2 via m16n8k16 fp16 mma,
//            2-term split: inner rounded to fp16 (Ah), W1 split hi/lo:
//            D = Ah*Bh + Ah*Bl  (dropped Al*B ~2^-12 rel).
//            Pairs as 160 segments (row i, 16-aligned j-block); xi broadcast,
//            xj LDS.128 via permuted x layout.
//   Phase 2: softmax over 2016.
//   Phase 3: out = 0.5 * colsum( x .* (W@x) ), W = symmetrized attn,
//            bf16 3-term mma (unchanged, validated).

#define NF 64
#define EDIM 64
#define ADIM 32
#define NPAIR 2016
#define XSTR 68
#define XPS 72
#define WPS 44
#define NTHREADS 256
#define NSEGT 160

// dynamic smem layout (bytes)
#define OFF_XS   0          // float[64*68]  = 17408 (PERMUTED cols)
#define OFF_W1H  17408      // u32[32*33]    = 4224  (fp16x2 hi)
#define OFF_W1L  21632      // u32[32*33]    = 4224  (fp16x2 lo)
#define OFF_LG   25856      // float[2048]   = 8192
#define OFF_IJP  34048      // u16[2048]     = 4096
#define OFF_XPH  38144      // u32[32*72]    = 9216  (bf16x2)
#define OFF_XPL  47360      // u32[32*72]    = 9216
#define OFF_WPH  56576      // u32[64*44]    = 11264
#define OFF_WPL  67840      // u32[64*44]    = 11264
#define OFF_SEG  79104      // u32[160]      = 640
#define OFF_MISC 79744
#define SMEM_DYN 80064

typedef unsigned long long ull;

__device__ __forceinline__ ull pk2(float lo, float hi) {
    ull r; asm("mov.b64 %0, {%1, %2};" : "=l"(r) : "f"(lo), "f"(hi)); return r;
}
__device__ __forceinline__ void up2(ull v, float& lo, float& hi) {
    asm("mov.b64 {%0, %1}, %2;" : "=f"(lo), "=f"(hi) : "l"(v));
}
__device__ __forceinline__ ull fma2(ull a, ull b, ull c) {
    ull d; asm("fma.rn.f32x2 %0, %1, %2, %3;" : "=l"(d) : "l"(a), "l"(b), "l"(c)); return d;
}
__device__ __forceinline__ uint32_t bf2(float vhi, float vlo) {
    uint32_t r; asm("cvt.rn.bf16x2.f32 %0, %1, %2;" : "=r"(r) : "f"(vhi), "f"(vlo)); return r;
}
__device__ __forceinline__ uint32_t hf2(float vhi, float vlo) {
    uint32_t r; asm("cvt.rn.f16x2.f32 %0, %1, %2;" : "=r"(r) : "f"(vhi), "f"(vlo)); return r;
}
// fp16 mma m16n8k16
__device__ __forceinline__ void mma_h(float* c, uint32_t a0, uint32_t a1,
                                      uint32_t a2, uint32_t a3,
                                      uint32_t b0, uint32_t b1) {
    asm volatile(
        "mma.sync.aligned.m16n8k16.row.col.f32.f16.f16.f32 "
        "{%0,%1,%2,%3}, {%4,%5,%6,%7}, {%8,%9}, {%0,%1,%2,%3};"
        : "+f"(c[0]), "+f"(c[1]), "+f"(c[2]), "+f"(c[3])
        : "r"(a0), "r"(a1), "r"(a2), "r"(a3), "r"(b0), "r"(b1));
}
// bf16 mma m16n8k16 (phase 3)
__device__ __forceinline__ void mma_b(float* c, uint32_t a0, uint32_t a1,
                                      uint32_t a2, uint32_t a3,
                                      uint32_t b0, uint32_t b1) {
    asm volatile(
        "mma.sync.aligned.m16n8k16.row.col.f32.bf16.bf16.f32 "
        "{%0,%1,%2,%3}, {%4,%5,%6,%7}, {%8,%9}, {%0,%1,%2,%3};"
        : "+f"(c[0]), "+f"(c[1]), "+f"(c[2]), "+f"(c[3])
        : "r"(a0), "r"(a1), "r"(a2), "r"(a3), "r"(b0), "r"(b1));
}
// column permutation within a 16-block: [0,1,8,9, 2,3,10,11, 4,5,12,13, 6,7,14,15]
__device__ __forceinline__ int pcol(int e) {
    int w = e & 15;
    return (e & 48) + ((w >> 1) & 3) * 4 + (w & 1) + ((w >> 3) << 1);
}

__global__ __launch_bounds__(NTHREADS, 2)
void afm_kernel(const float* __restrict__ x,    // (B, 64, 64)
                const float* __restrict__ W1,   // (64, 32)
                const float* __restrict__ b1,   // (32)
                const float* __restrict__ W2,   // (32, 1)
                const float* __restrict__ b2,   // (1)
                float* __restrict__ outP,       // (B, 64) or null
                float* __restrict__ attnP)      // (B, 2016) or null
{
    extern __shared__ char smx[];
    float*          xs   = (float*)(smx + OFF_XS);      // permuted
    uint32_t*       W1h  = (uint32_t*)(smx + OFF_W1H);  // fp16x2
    uint32_t*       W1l  = (uint32_t*)(smx + OFF_W1L);
    float*          lg   = (float*)(smx + OFF_LG);
    unsigned short* ijp  = (unsigned short*)(smx + OFF_IJP);
    uint32_t*       Xph  = (uint32_t*)(smx + OFF_XPH);
    uint32_t*       Xpl  = (uint32_t*)(smx + OFF_XPL);
    uint32_t*       Wph  = (uint32_t*)(smx + OFF_WPH);
    uint32_t*       Wpl  = (uint32_t*)(smx + OFF_WPL);
    uint32_t*       segt = (uint32_t*)(smx + OFF_SEG);
    uint16_t*       Wph16 = (uint16_t*)Wph;
    uint16_t*       Wpl16 = (uint16_t*)Wpl;
    float*          b1s  = (float*)(smx + OFF_MISC);
    float*          w2s  = b1s + 32;
    float*          red  = w2s + 32;
    float*          b2sp = red + 8;

    const int t    = threadIdx.x;
    const int lane = t & 31;
    const int warp = t >> 5;
    const int b    = blockIdx.x;

    // ======================= prologue ======================================
    const float* xb = x + (size_t)b * (NF * EDIM);
    for (int idx = t; idx < NF * EDIM; idx += NTHREADS) {
        int f = idx >> 6, e = idx & 63;
        xs[f * XSTR + pcol(e)] = xb[idx];
    }
    // Xp: packed bf16x2 over field pairs (phase 3 operand)
    for (int idx = t; idx < 32 * 64; idx += NTHREADS) {
        int j2 = idx >> 6, e = idx & 63;
        float v0 = xb[(2 * j2) * EDIM + e];
        float v1 = xb[(2 * j2 + 1) * EDIM + e];
        uint32_t hi = bf2(v1, v0);
        float h0 = __uint_as_float(hi << 16);
        float h1 = __uint_as_float(hi & 0xFFFF0000u);
        Xph[j2 * XPS + e] = hi;
        Xpl[j2 * XPS + e] = bf2(v1 - h1, v0 - h0);
    }
    // W1 fp16 hi/lo: word[e2][a] = {W1[2e2+1][a] hi-half, W1[2e2][a] lo-half}
    for (int idx = t; idx < 32 * 32; idx += NTHREADS) {
        int e2 = idx >> 5, a = idx & 31;
        float v0 = W1[(2 * e2) * ADIM + a];
        float v1 = W1[(2 * e2 + 1) * ADIM + a];
        uint32_t hi = hf2(v1, v0);
        __half2 h2 = *(__half2*)&hi;
        float2 back = __half22float2(h2);      // x = lo(v0), y = hi(v1)
        W1h[e2 * 33 + a] = hi;
        W1l[e2 * 33 + a] = hf2(v1 - back.y, v0 - back.x);
    }
    // zero attn matrices
    for (int idx = t; idx < 64 * WPS; idx += NTHREADS) {
        Wph[idx] = 0u;
        Wpl[idx] = 0u;
    }
    if (t < ADIM) { b1s[t] = b1[t]; w2s[t] = W2[t]; }
    if (t == 0)   { b2sp[0] = b2[0]; }
    // pair table + segment table
    if (t < NF - 1) {
        int i = t;
        int offi = i * 63 - (i * (i - 1)) / 2;
        for (int k = 0; k < NF - 1 - i; k++)
            ijp[offi + k] = (unsigned short)((i << 8) | (i + 1 + k));
        int q = i >> 4, r = i & 15;
        int S = 16 * (q * (q - 1) / 2) + q * (r + 1);
        int segbase = 4 * i - S;
        int first = (i + 1) >> 4;
        for (int s = first; s < 4; s++)
            segt[segbase + (s - first)] =
                (uint32_t)i | ((uint32_t)s << 6) | ((uint32_t)offi << 8);
    }
    if (t == 63) {
        for (int s = 0; s < 4; s++) segt[156 + s] = 63u | (3u << 6);
    }
    if (t >= 224) ijp[NPAIR + (t - 224)] = 0;
    __syncthreads();

    const float b2v = b2sp[0];
    const int tg = lane & 3;
    const int gr = lane >> 2;

    // hoisted B fragments (fp16 hi+lo) + epilogue constants
    uint32_t bh0[4][4], bh1[4][4], bl0[4][4], bl1[4][4];
    #pragma unroll
    for (int kb = 0; kb < 4; kb++) {
        #pragma unroll
        for (int nb = 0; nb < 4; nb++) {
            int e2 = kb * 8 + tg;
            int a  = nb * 8 + gr;
            bh0[kb][nb] = W1h[e2 * 33 + a];
            bh1[kb][nb] = W1h[(e2 + 4) * 33 + a];
            bl0[kb][nb] = W1l[e2 * 33 + a];
            bl1[kb][nb] = W1l[(e2 + 4) * 33 + a];
        }
    }
    float b1v0[4], b1v1[4], w2v0[4], w2v1[4];
    #pragma unroll
    for (int nb = 0; nb < 4; nb++) {
        int a = nb * 8 + tg * 2;
        b1v0[nb] = b1s[a];     b1v1[nb] = b1s[a + 1];
        w2v0[nb] = w2s[a];     w2v1[nb] = w2s[a + 1];
    }

    // ================= Phase 1: logits via fp16 mma (segments) =============
    for (int tt = 0; tt < NSEGT / 8; tt++) {
        const uint32_t sv = segt[tt * 8 + warp];
        const int i    = sv & 63;
        const int jb   = ((sv >> 6) & 3) << 4;
        const int offi = sv >> 8;

        const ulonglong2* xiP  = (const ulonglong2*)(xs + i * XSTR) + tg;
        const ulonglong2* xj0P = (const ulonglong2*)(xs + (jb + gr) * XSTR) + tg;
        const ulonglong2* xj1P = (const ulonglong2*)(xs + (jb + gr + 8) * XSTR) + tg;

        float c[4][4];
        #pragma unroll
        for (int nb = 0; nb < 4; nb++)
            c[nb][0] = c[nb][1] = c[nb][2] = c[nb][3] = 0.f;

        #pragma unroll
        for (int kb = 0; kb < 4; kb++) {
            const ulonglong2 xiv = xiP[kb * 4];
            const ulonglong2 xj0 = xj0P[kb * 4];
            const ulonglong2 xj1 = xj1P[kb * 4];
            ull prA = fma2(xj0.x, xiv.x, 0ull);     // row gr,   k low pair
            ull prB = fma2(xj0.y, xiv.y, 0ull);     // row gr,   k high pair
            ull prC = fma2(xj1.x, xiv.x, 0ull);     // row gr+8, k low pair
            ull prD = fma2(xj1.y, xiv.y, 0ull);     // row gr+8, k high pair
            float v0, v1;
            up2(prA, v0, v1); const uint32_t a0 = hf2(v1, v0);
            up2(prC, v0, v1); const uint32_t a1 = hf2(v1, v0);
            up2(prB, v0, v1); const uint32_t a2 = hf2(v1, v0);
            up2(prD, v0, v1); const uint32_t a3 = hf2(v1, v0);
            #pragma unroll
            for (int nb = 0; nb < 4; nb++) {
                mma_h(c[nb], a0, a1, a2, a3, bh0[kb][nb], bh1[kb][nb]);
                mma_h(c[nb], a0, a1, a2, a3, bl0[kb][nb], bl1[kb][nb]);
            }
        }

        float s_lo = 0.f, s_hi = 0.f;
        #pragma unroll
        for (int nb = 0; nb < 4; nb++) {
            s_lo = fmaf(fmaxf(c[nb][0] + b1v0[nb], 0.f), w2v0[nb], s_lo);
            s_lo = fmaf(fmaxf(c[nb][1] + b1v1[nb], 0.f), w2v1[nb], s_lo);
            s_hi = fmaf(fmaxf(c[nb][2] + b1v0[nb], 0.f), w2v0[nb], s_hi);
            s_hi = fmaf(fmaxf(c[nb][3] + b1v1[nb], 0.f), w2v1[nb], s_hi);
        }
        s_lo += __shfl_xor_sync(0xFFFFFFFFu, s_lo, 1);
        s_lo += __shfl_xor_sync(0xFFFFFFFFu, s_lo, 2);
        s_hi += __shfl_xor_sync(0xFFFFFFFFu, s_hi, 1);
        s_hi += __shfl_xor_sync(0xFFFFFFFFu, s_hi, 2);
        if (tg == 0) {
            const int j0 = jb + gr;
            const int j1 = jb + gr + 8;
            if (j0 > i) lg[offi + j0 - i - 1] = s_lo + b2v;
            if (j1 > i) lg[offi + j1 - i - 1] = s_hi + b2v;
        }
    }
    __syncthreads();

    // ================= Phase 2: softmax ====================================
    float lmax = -3.402823466e+38f;
    for (int p = t; p < NPAIR; p += NTHREADS) lmax = fmaxf(lmax, lg[p]);
    #pragma unroll
    for (int o = 16; o > 0; o >>= 1) lmax = fmaxf(lmax, __shfl_xor_sync(0xFFFFFFFFu, lmax, o));
    if (lane == 0) red[warp] = lmax;
    __syncthreads();
    if (t == 0) {
        float m = red[0];
        #pragma unroll
        for (int w = 1; w < 8; w++) m = fmaxf(m, red[w]);
        red[0] = m;
    }
    __syncthreads();
    const float gmax = red[0];
    __syncthreads();

    float lsum = 0.f;
    for (int p = t; p < NPAIR; p += NTHREADS) {
        float ev = expf(lg[p] - gmax);
        lg[p] = ev;
        lsum += ev;
    }
    #pragma unroll
    for (int o = 16; o > 0; o >>= 1) lsum += __shfl_xor_sync(0xFFFFFFFFu, lsum, o);
    if (lane == 0) red[warp] = lsum;
    __syncthreads();
    if (t == 0) {
        float s = 0.f;
        #pragma unroll
        for (int w = 0; w < 8; w++) s += red[w];
        red[0] = 1.0f / s;
    }
    __syncthreads();
    const float inv = red[0];

    // normalize + emit attn + scatter symmetric W (bf16 hi/lo)
    for (int p = t; p < NPAIR; p += NTHREADS) {
        float av = lg[p] * inv;
        if (attnP) attnP[(size_t)b * NPAIR + p] = av;
        const unsigned short ij = ijp[p];
        const int i = ij >> 8, j = ij & 255;
        uint32_t hpair = bf2(0.f, av);
        uint16_t hb = (uint16_t)(hpair & 0xFFFFu);
        float hv = __uint_as_float((uint32_t)hb << 16);
        uint32_t lpair = bf2(0.f, av - hv);
        uint16_t lb = (uint16_t)(lpair & 0xFFFFu);
        Wph16[i * (2 * WPS) + j] = hb;
        Wph16[j * (2 * WPS) + i] = hb;
        Wpl16[i * (2 * WPS) + j] = lb;
        Wpl16[j * (2 * WPS) + i] = lb;
    }
    __syncthreads();

    // ================= Phase 3: out = 0.5 * colsum(x .* (W@x)) =============
    if (outP) {
        float c[4][4];
        #pragma unroll
        for (int m = 0; m < 4; m++)
            c[m][0] = c[m][1] = c[m][2] = c[m][3] = 0.f;

        const int ecol = warp * 8 + gr;
        #pragma unroll
        for (int kb = 0; kb < 4; kb++) {
            const int j2a = kb * 8 + tg;
            uint32_t xh0 = Xph[j2a * XPS + ecol];
            uint32_t xh1 = Xph[(j2a + 4) * XPS + ecol];
            uint32_t xl0 = Xpl[j2a * XPS + ecol];
            uint32_t xl1 = Xpl[(j2a + 4) * XPS + ecol];
            #pragma unroll
            for (int m = 0; m < 4; m++) {
                const int r0 = (m * 16 + gr) * WPS;
                const int r1 = (m * 16 + gr + 8) * WPS;
                uint32_t ah0 = Wph[r0 + j2a];
                uint32_t ah1 = Wph[r1 + j2a];
                uint32_t ah2 = Wph[r0 + j2a + 4];
                uint32_t ah3 = Wph[r1 + j2a + 4];
                uint32_t al0 = Wpl[r0 + j2a];
                uint32_t al1 = Wpl[r1 + j2a];
                uint32_t al2 = Wpl[r0 + j2a + 4];
                uint32_t al3 = Wpl[r1 + j2a + 4];
                mma_b(c[m], ah0, ah1, ah2, ah3, xh0, xh1);
                mma_b(c[m], ah0, ah1, ah2, ah3, xl0, xl1);
                mma_b(c[m], al0, al1, al2, al3, xh0, xh1);
            }
        }

        const int e0 = warp * 8 + tg * 2;
        const int pe = pcol(e0);
        float pe0 = 0.f, pe1 = 0.f;
        #pragma unroll
        for (int m = 0; m < 4; m++) {
            const int i0 = m * 16 + gr;
            const int i1 = i0 + 8;
            float x00, x01, x10, x11;
            up2(*(const ull*)(xs + i0 * XSTR + pe), x00, x01);
            up2(*(const ull*)(xs + i1 * XSTR + pe), x10, x11);
            pe0 = fmaf(c[m][0], x00, pe0);
            pe1 = fmaf(c[m][1], x01, pe1);
            pe0 = fmaf(c[m][2], x10, pe0);
            pe1 = fmaf(c[m][3], x11, pe1);
        }
        #pragma unroll
        for (int o = 4; o < 32; o <<= 1) {
            pe0 += __shfl_xor_sync(0xFFFFFFFFu, pe0, o);
            pe1 += __shfl_xor_sync(0xFFFFFFFFu, pe1, o);
        }
        if (gr == 0) {
            outP[(size_t)b * EDIM + e0]     = 0.5f * pe0;
            outP[(size_t)b * EDIM + e0 + 1] = 0.5f * pe1;
        }
    }
}

extern "C" void kernel_launch(void* const* d_in, const int* in_sizes, int n_in,
                              void* d_out, int out_size) {
    const float* x  = (const float*)d_in[0];
    const float* W1 = (const float*)d_in[1];
    const float* b1 = (const float*)d_in[2];
    const float* W2 = (const float*)d_in[3];
    const float* b2 = (const float*)d_in[4];

    const int B = in_sizes[0] / (NF * EDIM);

    float* outP  = (float*)d_out;
    float* attnP = (float*)d_out + (size_t)B * EDIM;
    if (out_size == B * NPAIR) {           // attn only
        attnP = (float*)d_out;
        outP  = nullptr;
    } else if (out_size == B * EDIM) {     // outputs only
        attnP = nullptr;
    }

    cudaFuncSetAttribute(afm_kernel, cudaFuncAttributeMaxDynamicSharedMemorySize, SMEM_DYN);
    afm_kernel<<<B, NTHREADS, SMEM_DYN>>>(x, W1, b1, W2, b2, outP, attnP);
}